// round 7
// baseline (speedup 1.0000x reference)
#include <cuda_runtime.h>
#include <math.h>

#define HH 496
#define WW 432
#define HW (HH*WW)            // 214272
#define APL 6
#define NANCH (HW*APL)        // 1285632
#define KPRE 4096
#define MAXN 500
#define SCORE_THR 0.1f
#define NMS_THR 0.5f
#define CAND_CAP (1<<18)
#define TIE_CAP 4096
#define PI_F 3.14159265358979323846f
#define PIH_F 1.57079632679489661923f

// ---------------- device scratch (static, no allocations) ----------------
__device__ unsigned g_key[NANCH];            // layout [a][HW]
__device__ unsigned g_hist[65536];
__device__ unsigned g_hist2[65536];
__device__ int g_cntHi;
__device__ int g_candCnt;
__device__ int g_tieCnt;
__device__ int g_thr1;
__device__ int g_k2;
__device__ unsigned g_cand_key[CAND_CAP];
__device__ int      g_cand_idx[CAND_CAP];
__device__ int      g_tie[TIE_CAP];
__device__ int      g_topk_idx[KPRE];        // original flat index s*APL+a
__device__ unsigned g_topk_key[KPRE];
__device__ float    g_sc[KPRE*3];
__device__ float    g_dirf[KPRE];
__device__ float    g_box[KPRE*7];
__device__ float4   g_xyxy[KPRE];
__device__ int      g_sorted_slot[3*KPRE];
__device__ float    g_sorted_score[3*KPRE];
__device__ float4   g_sxy[3*KPRE];           // box by rank
__device__ unsigned g_nms_rank[3*KPRE];      // spatial order: rank | invalid-bit
__device__ float4   g_nms_box[3*KPRE];       // box by spatial pos
__device__ int      g_kept_slot[3*MAXN];
__device__ float    g_kept_score[3*MAXN];
__device__ int      g_kept_cnt[3];

__device__ __forceinline__ float sigd(float x) {
    // double-rounded sigmoid: matches fp32 reference sigmoid to <=1ulp
    return (float)(1.0 / (1.0 + exp(-(double)x)));
}

__device__ __forceinline__ unsigned mono_key(float m) {
    // order-preserving map fp32 -> u32 (sigmoid is monotone in the logit)
    unsigned b = __float_as_uint(m);
    return (b & 0x80000000u) ? ~b : (b | 0x80000000u);
}

__device__ __forceinline__ float area_rn(float x1, float y1, float x2, float y2) {
    return __fmul_rn(__fadd_rn(__fsub_rn(x2, x1), 1.f),
                     __fadd_rn(__fsub_rn(y2, y1), 1.f));
}

// ---------------- kernel 0: zero scratch ----------------
__global__ void zero_kernel() {
    int t = blockIdx.x * blockDim.x + threadIdx.x;
    if (t < 65536) { g_hist[t] = 0u; g_hist2[t] = 0u; }
    if (t == 0) { g_cntHi = 0; g_candCnt = 0; g_tieCnt = 0; }
}

// ---------------- kernel 1: per-anchor max-logit key + histogram (vectorized) ----------------
__global__ void score_hist(const float* __restrict__ cls) {
    int t = blockIdx.x * blockDim.x + threadIdx.x;
    if (t >= HW/4) return;
    int s = t * 4;
#pragma unroll
    for (int a = 0; a < APL; a++) {
        const float4 v0 = *reinterpret_cast<const float4*>(cls + (size_t)(a*3+0)*HW + s);
        const float4 v1 = *reinterpret_cast<const float4*>(cls + (size_t)(a*3+1)*HW + s);
        const float4 v2 = *reinterpret_cast<const float4*>(cls + (size_t)(a*3+2)*HW + s);
        unsigned k0 = mono_key(fmaxf(fmaxf(v0.x, v1.x), v2.x));
        unsigned k1 = mono_key(fmaxf(fmaxf(v0.y, v1.y), v2.y));
        unsigned k2 = mono_key(fmaxf(fmaxf(v0.z, v1.z), v2.z));
        unsigned k3 = mono_key(fmaxf(fmaxf(v0.w, v1.w), v2.w));
        *reinterpret_cast<uint4*>(g_key + (size_t)a*HW + s) = make_uint4(k0, k1, k2, k3);
        atomicAdd(&g_hist[k0 >> 16], 1u);
        atomicAdd(&g_hist[k1 >> 16], 1u);
        atomicAdd(&g_hist[k2 >> 16], 1u);
        atomicAdd(&g_hist[k3 >> 16], 1u);
    }
}

// ---------------- kernel 2: find level-1 threshold bin ----------------
__global__ void __launch_bounds__(1024) find_thr1() {
    __shared__ unsigned csum[1024];
    unsigned ssum = 0;
    int base = threadIdx.x * 64;
    for (int b = 0; b < 64; b++) ssum += g_hist[base + b];
    csum[threadIdx.x] = ssum;
    __syncthreads();
    if (threadIdx.x == 0) {
        unsigned acc = 0; int ch;
        for (ch = 1023; ch >= 0; ch--) {
            if (acc + csum[ch] >= (unsigned)KPRE) break;
            acc += csum[ch];
        }
        unsigned C1 = acc; int T = ch * 64;
        for (int b = 63; b >= 0; b--) {
            unsigned h = g_hist[ch*64 + b];
            if (C1 + h >= (unsigned)KPRE) { T = ch*64 + b; break; }
            C1 += h;
        }
        g_thr1 = T;
        g_k2 = KPRE - (int)C1;
    }
}

// ---------------- kernel 3: compact winners + boundary candidates (vectorized) ----------------
__global__ void compact1() {
    int p = blockIdx.x * blockDim.x + threadIdx.x;
    if (p >= NANCH/4) return;
    uint4 kv = *reinterpret_cast<const uint4*>(g_key + 4*(size_t)p);
    unsigned ks[4] = {kv.x, kv.y, kv.z, kv.w};
    int T = g_thr1;
#pragma unroll
    for (int j = 0; j < 4; j++) {
        unsigned key = ks[j];
        int bin = (int)(key >> 16);
        if (bin >= T) {
            int pos = 4*p + j;             // position in [a][HW] layout
            int a = pos / HW, s = pos - a*HW;
            int iorig = s*APL + a;
            if (bin > T) {
                int q = atomicAdd(&g_cntHi, 1);
                g_topk_idx[q] = iorig; g_topk_key[q] = key;
            } else {
                int q = atomicAdd(&g_candCnt, 1);
                if (q < CAND_CAP) { g_cand_key[q] = key; g_cand_idx[q] = iorig; }
            }
        }
    }
}

// ---------------- kernel 4: level-2 refinement + exact tie-break ----------------
__global__ void __launch_bounds__(1024) level2() {
    __shared__ unsigned csum[1024];
    __shared__ int sT2, sk3;
    int nc = min(g_candCnt, CAND_CAP);
    int k2 = g_k2;
    for (int t = threadIdx.x; t < nc; t += 1024)
        atomicAdd(&g_hist2[g_cand_key[t] & 0xFFFFu], 1u);
    __syncthreads();
    unsigned ssum = 0; int base = threadIdx.x * 64;
    for (int b = 0; b < 64; b++) ssum += g_hist2[base + b];
    csum[threadIdx.x] = ssum;
    __syncthreads();
    if (threadIdx.x == 0) {
        unsigned acc = 0; int ch;
        for (ch = 1023; ch >= 0; ch--) {
            if (acc + csum[ch] >= (unsigned)k2) break;
            acc += csum[ch];
        }
        unsigned C1 = acc; int T = ch * 64;
        for (int b = 63; b >= 0; b--) {
            unsigned h = g_hist2[ch*64 + b];
            if (C1 + h >= (unsigned)k2) { T = ch*64 + b; break; }
            C1 += h;
        }
        sT2 = T; sk3 = k2 - (int)C1;
    }
    __syncthreads();
    int T2 = sT2;
    for (int t = threadIdx.x; t < nc; t += 1024) {
        int low = (int)(g_cand_key[t] & 0xFFFFu);
        if (low > T2) {
            int p = atomicAdd(&g_cntHi, 1);
            g_topk_idx[p] = g_cand_idx[t];
            g_topk_key[p] = g_cand_key[t];
        } else if (low == T2) {
            int p = atomicAdd(&g_tieCnt, 1);
            if (p < TIE_CAP) g_tie[p] = g_cand_idx[t];
        }
    }
    __syncthreads();
    int m = min(g_tieCnt, TIE_CAP);
    int k3 = sk3;
    unsigned tie_key = ((unsigned)g_thr1 << 16) | (unsigned)T2;
    for (int t = threadIdx.x; t < m; t += 1024) {
        int idx = g_tie[t];
        int rank = 0;
        for (int u = 0; u < m; u++) rank += (g_tie[u] < idx) ? 1 : 0;
        if (rank < k3) {
            int p = atomicAdd(&g_cntHi, 1);
            g_topk_idx[p] = idx; g_topk_key[p] = tie_key;
        }
    }
}

// ---------------- kernel 4b: canonicalize top-k order (key desc, idx asc) ----------------
__global__ void __launch_bounds__(1024) sort_topk() {
    __shared__ unsigned long long sm[KPRE];
    for (int t = threadIdx.x; t < KPRE; t += 1024) {
        sm[t] = ((unsigned long long)g_topk_key[t] << 32) | (unsigned)(~(unsigned)g_topk_idx[t]);
    }
    __syncthreads();
    for (unsigned k = 2; k <= KPRE; k <<= 1) {
        for (unsigned j = k >> 1; j > 0; j >>= 1) {
            for (unsigned t = threadIdx.x; t < KPRE; t += 1024) {
                unsigned ixj = t ^ j;
                if (ixj > t) {
                    unsigned long long A = sm[t], B = sm[ixj];
                    if ((A < B) == ((t & k) == 0)) { sm[t] = B; sm[ixj] = A; }  // descending
                }
            }
            __syncthreads();
        }
    }
    for (int t = threadIdx.x; t < KPRE; t += 1024)
        g_topk_idx[t] = (int)(~(unsigned)(sm[t] & 0xFFFFFFFFu));
}

// ---------------- kernel 5: gather + decode the 4096 selected anchors ----------------
__global__ void decode_kernel(const float* __restrict__ cls, const float* __restrict__ bp,
                              const float* __restrict__ dirp, const float* __restrict__ priors) {
    int t = blockIdx.x * blockDim.x + threadIdx.x;
    if (t >= KPRE) return;
    int i = g_topk_idx[t];
    int s = i / APL, a = i - s * APL;
#pragma unroll
    for (int c = 0; c < 3; c++)
        g_sc[t*3 + c] = sigd(cls[(a*3 + c)*HW + s]);
    float dv0 = dirp[(a*2 + 0)*HW + s];
    float dv1 = dirp[(a*2 + 1)*HW + s];
    g_dirf[t] = (dv1 > dv0) ? 1.f : 0.f;

    float dl[7], an[7];
#pragma unroll
    for (int k = 0; k < 7; k++) {
        dl[k] = bp[(a*7 + k)*HW + s];
        an[k] = priors[(size_t)i*7 + k];
    }
    float za   = __fadd_rn(an[2], __fmul_rn(an[5], 0.5f));
    float diag = sqrtf(__fadd_rn(__fmul_rn(an[4], an[4]), __fmul_rn(an[3], an[3])));
    float xg = __fadd_rn(__fmul_rn(dl[0], diag), an[0]);
    float yg = __fadd_rn(__fmul_rn(dl[1], diag), an[1]);
    float zg = __fadd_rn(__fmul_rn(dl[2], an[5]), za);
    float wg = __fmul_rn(expf(dl[3]), an[3]);
    float lg = __fmul_rn(expf(dl[4]), an[4]);
    float hg = __fmul_rn(expf(dl[5]), an[5]);
    float rg = __fadd_rn(dl[6], an[6]);
    zg = __fsub_rn(zg, __fmul_rn(hg, 0.5f));
    g_box[t*7+0]=xg; g_box[t*7+1]=yg; g_box[t*7+2]=zg;
    g_box[t*7+3]=wg; g_box[t*7+4]=lg; g_box[t*7+5]=hg; g_box[t*7+6]=rg;
    g_xyxy[t] = make_float4(__fsub_rn(xg, __fmul_rn(wg, 0.5f)),
                            __fsub_rn(yg, __fmul_rn(lg, 0.5f)),
                            __fadd_rn(xg, __fmul_rn(wg, 0.5f)),
                            __fadd_rn(yg, __fmul_rn(lg, 0.5f)));
}

// ---------------- kernel 6: per-class score sort + spatial permutation ----------------
__global__ void __launch_bounds__(1024) sort_class() {
    int c = blockIdx.x;
    __shared__ unsigned long long sm[KPRE];
    // phase 1: sort by (score desc, topk-pos asc)
    for (int t = threadIdx.x; t < KPRE; t += 1024) {
        float sc = g_sc[t*3 + c];
        sm[t] = ((unsigned long long)__float_as_uint(sc) << 32) | (unsigned)(~(unsigned)t);
    }
    __syncthreads();
    for (unsigned k = 2; k <= KPRE; k <<= 1) {
        for (unsigned j = k >> 1; j > 0; j >>= 1) {
            for (unsigned t = threadIdx.x; t < KPRE; t += 1024) {
                unsigned ixj = t ^ j;
                if (ixj > t) {
                    unsigned long long A = sm[t], B = sm[ixj];
                    if ((A < B) == ((t & k) == 0)) { sm[t] = B; sm[ixj] = A; }
                }
            }
            __syncthreads();
        }
    }
    unsigned k2loc[4];
    {
        int q = 0;
        for (int t = threadIdx.x; t < KPRE; t += 1024, q++) {
            unsigned long long key = sm[t];
            int slot = (int)(~(unsigned)(key & 0xFFFFFFFFu));
            float sc = __uint_as_float((unsigned)(key >> 32));
            g_sorted_slot[c*KPRE + t] = slot;
            g_sorted_score[c*KPRE + t] = sc;
            float4 b = g_xyxy[slot];
            g_sxy[c*KPRE + t] = b;
            // spatial cell key (4m cells), payload = rank t
            float cx = (b.x + b.z) * 0.5f, cy = (b.y + b.w) * 0.5f;
            int ix = min(31, max(0, (int)(cx * 0.25f)));
            int iy = min(31, max(0, (int)((cy + 40.f) * 0.25f)));
            k2loc[q] = ((unsigned)(iy*32 + ix) << 12) | (unsigned)t;
        }
    }
    __syncthreads();
    // phase 2: bitonic ascending sort of spatial keys
    unsigned* sm32 = (unsigned*)sm;
    {
        int q = 0;
        for (int t = threadIdx.x; t < KPRE; t += 1024, q++) sm32[t] = k2loc[q];
    }
    __syncthreads();
    for (unsigned k = 2; k <= KPRE; k <<= 1) {
        for (unsigned j = k >> 1; j > 0; j >>= 1) {
            for (unsigned t = threadIdx.x; t < KPRE; t += 1024) {
                unsigned ixj = t ^ j;
                if (ixj > t) {
                    unsigned A = sm32[t], B = sm32[ixj];
                    if ((A > B) == ((t & k) == 0)) { sm32[t] = B; sm32[ixj] = A; }  // ascending
                }
            }
            __syncthreads();
        }
    }
    for (int t = threadIdx.x; t < KPRE; t += 1024) {
        int r = (int)(sm32[t] & 0xFFFu);
        float4 b = g_sxy[c*KPRE + r];
        float sc = g_sorted_score[c*KPRE + r];
        g_nms_rank[c*KPRE + t] = (unsigned)r | (sc > SCORE_THR ? 0u : 0x80000000u);
        g_nms_box[c*KPRE + t] = b;
    }
}

// ---------------- kernel 7: greedy NMS — bitmap pick + hierarchical spatial reject ----------------
__global__ void __launch_bounds__(1024) nms_reduce() {
    int c = blockIdx.x;
    int tid = threadIdx.x;
    __shared__ unsigned long long remv[64];   // by rank: removed OR invalid
    __shared__ short s_r2p[KPRE];             // rank -> spatial pos
    __shared__ int s_keptrank[MAXN];
    __shared__ int s_pos, s_irank;
    __shared__ float s_ref[8];                // x1,y1,x2,y2,area,cx,cy,rad

    // register-resident: 4 spatially-contiguous boxes per thread
    float4 bx[4]; float cxk[4], cyk[4], rdk[4]; int rk[4]; bool alive[4];
    int base = c*KPRE + tid*4;
#pragma unroll
    for (int k = 0; k < 4; k++) {
        float4 b = g_nms_box[base + k];
        bx[k] = b;
        cxk[k] = (b.x + b.z) * 0.5f;
        cyk[k] = (b.y + b.w) * 0.5f;
        rdk[k] = fmaxf((b.z - b.x) * 0.5f, (b.w - b.y) * 0.5f);
        unsigned r = g_nms_rank[base + k];
        rk[k] = (int)(r & 0x7FFFFFFFu);
        alive[k] = !(r >> 31);
    }
    if (tid < 64) remv[tid] = 0ull;
    __syncthreads();
#pragma unroll
    for (int k = 0; k < 4; k++) {
        s_r2p[rk[k]] = (short)(tid*4 + k);
        if (!alive[k]) atomicOr(&remv[rk[k] >> 6], 1ull << (rk[k] & 63));
    }
    // per-warp spatial bbox (over all 128 boxes of the warp)
    float wminx = cxk[0], wmaxx = cxk[0], wminy = cyk[0], wmaxy = cyk[0], wmaxr = rdk[0];
#pragma unroll
    for (int k = 1; k < 4; k++) {
        wminx = fminf(wminx, cxk[k]); wmaxx = fmaxf(wmaxx, cxk[k]);
        wminy = fminf(wminy, cyk[k]); wmaxy = fmaxf(wmaxy, cyk[k]);
        wmaxr = fmaxf(wmaxr, rdk[k]);
    }
#pragma unroll
    for (int o = 16; o > 0; o >>= 1) {
        wminx = fminf(wminx, __shfl_xor_sync(0xFFFFFFFFu, wminx, o));
        wmaxx = fmaxf(wmaxx, __shfl_xor_sync(0xFFFFFFFFu, wmaxx, o));
        wminy = fminf(wminy, __shfl_xor_sync(0xFFFFFFFFu, wminy, o));
        wmaxy = fmaxf(wmaxy, __shfl_xor_sync(0xFFFFFFFFu, wmaxy, o));
        wmaxr = fmaxf(wmaxr, __shfl_xor_sync(0xFFFFFFFFu, wmaxr, o));
    }
    __syncthreads();

    int cnt = 0;
    int wd0 = 0;   // thread0 only
    while (true) {
        if (tid == 0) {
            int found = -1;
            for (int wd = wd0; wd < 64; wd++) {
                unsigned long long avail = ~remv[wd];
                if (avail) { found = wd*64 + __ffsll((long long)avail) - 1; wd0 = wd; break; }
            }
            if (found >= 0) {
                remv[found >> 6] |= 1ull << (found & 63);
                s_keptrank[cnt] = found;
                s_irank = found;
                s_pos = (int)s_r2p[found];
            } else s_pos = -1;
        }
        __syncthreads();                       // bar1: s_pos/s_irank visible
        int pos = s_pos;
        if (pos < 0) break;
        int irank = s_irank;
        if (tid == (pos >> 2)) {               // owner publishes from registers
            int k = pos & 3;
            s_ref[0] = bx[k].x; s_ref[1] = bx[k].y;
            s_ref[2] = bx[k].z; s_ref[3] = bx[k].w;
            s_ref[4] = area_rn(bx[k].x, bx[k].y, bx[k].z, bx[k].w);
            s_ref[5] = cxk[k]; s_ref[6] = cyk[k]; s_ref[7] = rdk[k];
            alive[k] = false;
        }
        __syncthreads();                       // bar2: s_ref visible
        float rcx = s_ref[5], rcy = s_ref[6], rrad = s_ref[7];
        // warp-level conservative reject (uniform across warp)
        float ddx = fmaxf(fmaxf(wminx - rcx, rcx - wmaxx), 0.f);
        float ddy = fmaxf(fmaxf(wminy - rcy, rcy - wmaxy), 0.f);
        float reach = wmaxr + rrad + 1.5f;
        if (ddx <= reach && ddy <= reach) {
            bool pass[4]; bool anyp = false;
#pragma unroll
            for (int k = 0; k < 4; k++) {
                bool p = alive[k] && (rk[k] > irank)
                      && fabsf(cxk[k] - rcx) <= rdk[k] + rrad + 1.5f
                      && fabsf(cyk[k] - rcy) <= rdk[k] + rrad + 1.5f;
                pass[k] = p; anyp |= p;
            }
            if (__any_sync(0xFFFFFFFFu, anyp)) {
                float rx1 = s_ref[0], ry1 = s_ref[1], rx2 = s_ref[2], ry2 = s_ref[3], ra = s_ref[4];
#pragma unroll
                for (int k = 0; k < 4; k++) {
                    if (pass[k]) {
                        float xx1 = fmaxf(rx1, bx[k].x);
                        float yy1 = fmaxf(ry1, bx[k].y);
                        float xx2 = fminf(rx2, bx[k].z);
                        float yy2 = fminf(ry2, bx[k].w);
                        float w  = __fadd_rn(__fsub_rn(xx2, xx1), 1.f);
                        float h2 = __fadd_rn(__fsub_rn(yy2, yy1), 1.f);
                        if (w > 0.f && h2 > 0.f) {
                            float inter = __fmul_rn(w, h2);
                            float ark = area_rn(bx[k].x, bx[k].y, bx[k].z, bx[k].w);
                            float den = __fsub_rn(__fadd_rn(ra, ark), inter);
                            if (__fdiv_rn(inter, den) > NMS_THR) {
                                alive[k] = false;
                                atomicOr(&remv[rk[k] >> 6], 1ull << (rk[k] & 63));
                            }
                        }
                    }
                }
            }
        }
        __syncthreads();                       // bar3: remv updates visible to thread0
        cnt++;
        if (cnt >= MAXN) break;
    }
    // materialize kept list (gathers out of the serial loop)
    for (int r = tid; r < cnt; r += 1024) {
        int rkp = s_keptrank[r];
        g_kept_slot[c*MAXN + r]  = g_sorted_slot[c*KPRE + rkp];
        g_kept_score[c*MAXN + r] = g_sorted_score[c*KPRE + rkp];
    }
    if (tid == 0) g_kept_cnt[c] = cnt;
}

// ---------------- kernel 8: merge + final top-500 + output ----------------
__global__ void __launch_bounds__(1024) final_merge(float* __restrict__ out) {
    __shared__ unsigned long long sm[2048];
    for (int t = threadIdx.x; t < 2048; t += 1024) {
        unsigned long long key = 0ull;
        if (t < 3*MAXN) {
            int c = t / MAXN, pos = t % MAXN;
            if (pos < g_kept_cnt[c]) {
                float sc = g_kept_score[c*MAXN + pos];
                unsigned flat = (unsigned)(c*KPRE + pos);
                key = ((unsigned long long)__float_as_uint(sc) << 32) | (unsigned)(~flat);
            }
        }
        sm[t] = key;
    }
    __syncthreads();
    for (unsigned k = 2; k <= 2048; k <<= 1) {
        for (unsigned j = k >> 1; j > 0; j >>= 1) {
            for (unsigned t = threadIdx.x; t < 2048; t += 1024) {
                unsigned ixj = t ^ j;
                if (ixj > t) {
                    unsigned long long A = sm[t], B = sm[ixj];
                    if ((A < B) == ((t & k) == 0)) { sm[t] = B; sm[ixj] = A; }
                }
            }
            __syncthreads();
        }
    }
    for (int r = threadIdx.x; r < MAXN; r += 1024) {
        unsigned long long key = sm[r];
        if (key != 0ull) {
            float score = __uint_as_float((unsigned)(key >> 32));
            unsigned flat = ~(unsigned)(key & 0xFFFFFFFFu);
            int c = (int)(flat >> 12);
            int pos = (int)(flat & 4095u);
            int slot = g_kept_slot[c*MAXN + pos];
            float b[7];
#pragma unroll
            for (int k = 0; k < 7; k++) b[k] = g_box[slot*7 + k];
            float rr = b[6];
            float dir_rot = __fsub_rn(__fadd_rn(rr, PIH_F),
                                      __fmul_rn(floorf(__fadd_rn(rr, 0.5f)), PI_F));
            b[6] = __fadd_rn(__fsub_rn(dir_rot, PIH_F), __fmul_rn(PI_F, g_dirf[slot]));
#pragma unroll
            for (int k = 0; k < 7; k++) out[r*7 + k] = b[k];
            out[7*MAXN + r] = score;
            out[8*MAXN + r] = (float)c;
        } else {
#pragma unroll
            for (int k = 0; k < 7; k++) out[r*7 + k] = 0.f;
            out[7*MAXN + r] = 0.f;
            out[8*MAXN + r] = -1.f;
        }
    }
}

// ---------------- launch ----------------
extern "C" void kernel_launch(void* const* d_in, const int* in_sizes, int n_in,
                              void* d_out, int out_size) {
    const float* cls    = (const float*)d_in[0];
    const float* bp     = (const float*)d_in[1];
    const float* dirp   = (const float*)d_in[2];
    const float* priors = (const float*)d_in[3];
    float* out = (float*)d_out;

    zero_kernel<<<256, 256>>>();
    score_hist<<<(HW/4 + 255) / 256, 256>>>(cls);
    find_thr1<<<1, 1024>>>();
    compact1<<<(NANCH/4 + 255) / 256, 256>>>();
    level2<<<1, 1024>>>();
    sort_topk<<<1, 1024>>>();
    decode_kernel<<<(KPRE + 255) / 256, 256>>>(cls, bp, dirp, priors);
    sort_class<<<3, 1024>>>();
    nms_reduce<<<3, 1024>>>();
    final_merge<<<1, 1024>>>(out);
}

// round 8
// speedup vs baseline: 1.2676x; 1.2676x over previous
#include <cuda_runtime.h>
#include <math.h>

#define HH 496
#define WW 432
#define HW (HH*WW)            // 214272
#define APL 6
#define NANCH (HW*APL)        // 1285632
#define KPRE 4096
#define MAXN 500
#define SCORE_THR 0.1f
#define NMS_THR 0.5f
#define CAND_CAP (1<<18)
#define TIE_CAP 4096
#define PI_F 3.14159265358979323846f
#define PIH_F 1.57079632679489661923f

// ---------------- device scratch (static, no allocations) ----------------
__device__ unsigned g_key[NANCH];            // layout [a][HW]
__device__ unsigned g_hist[65536];
__device__ unsigned g_hist2[65536];
__device__ int g_cntHi;
__device__ int g_candCnt;
__device__ int g_tieCnt;
__device__ int g_thr1;
__device__ int g_k2;
__device__ unsigned g_cand_key[CAND_CAP];
__device__ int      g_cand_idx[CAND_CAP];
__device__ int      g_tie[TIE_CAP];
__device__ int      g_topk_idx[KPRE];        // original flat index s*APL+a
__device__ unsigned g_topk_key[KPRE];
__device__ float    g_sc[KPRE*3];
__device__ float    g_dirf[KPRE];
__device__ float    g_box[KPRE*7];
__device__ float4   g_xyxy[KPRE];
__device__ int      g_sorted_slot[3*KPRE];
__device__ float    g_sorted_score[3*KPRE];
__device__ float4   g_sxy[3*KPRE];
__device__ int      g_kept_slot[3*MAXN];
__device__ float    g_kept_score[3*MAXN];
__device__ int      g_kept_cnt[3];

__device__ __forceinline__ float sigd(float x) {
    // double-rounded sigmoid: matches fp32 reference sigmoid to <=1ulp
    return (float)(1.0 / (1.0 + exp(-(double)x)));
}

__device__ __forceinline__ unsigned mono_key(float m) {
    // order-preserving map fp32 -> u32 (sigmoid is monotone in the logit)
    unsigned b = __float_as_uint(m);
    return (b & 0x80000000u) ? ~b : (b | 0x80000000u);
}

__device__ __forceinline__ float area_rn(float x1, float y1, float x2, float y2) {
    return __fmul_rn(__fadd_rn(__fsub_rn(x2, x1), 1.f),
                     __fadd_rn(__fsub_rn(y2, y1), 1.f));
}

// ---------------- kernel 0: zero scratch ----------------
__global__ void zero_kernel() {
    int t = blockIdx.x * blockDim.x + threadIdx.x;
    if (t < 65536) { g_hist[t] = 0u; g_hist2[t] = 0u; }
    if (t == 0) { g_cntHi = 0; g_candCnt = 0; g_tieCnt = 0; }
}

// ---------------- kernel 1: per-anchor max-logit key + histogram (vectorized) ----------------
__global__ void score_hist(const float* __restrict__ cls) {
    int t = blockIdx.x * blockDim.x + threadIdx.x;
    if (t >= HW/4) return;
    int s = t * 4;
#pragma unroll
    for (int a = 0; a < APL; a++) {
        const float4 v0 = *reinterpret_cast<const float4*>(cls + (size_t)(a*3+0)*HW + s);
        const float4 v1 = *reinterpret_cast<const float4*>(cls + (size_t)(a*3+1)*HW + s);
        const float4 v2 = *reinterpret_cast<const float4*>(cls + (size_t)(a*3+2)*HW + s);
        unsigned k0 = mono_key(fmaxf(fmaxf(v0.x, v1.x), v2.x));
        unsigned k1 = mono_key(fmaxf(fmaxf(v0.y, v1.y), v2.y));
        unsigned k2 = mono_key(fmaxf(fmaxf(v0.z, v1.z), v2.z));
        unsigned k3 = mono_key(fmaxf(fmaxf(v0.w, v1.w), v2.w));
        *reinterpret_cast<uint4*>(g_key + (size_t)a*HW + s) = make_uint4(k0, k1, k2, k3);
        atomicAdd(&g_hist[k0 >> 16], 1u);
        atomicAdd(&g_hist[k1 >> 16], 1u);
        atomicAdd(&g_hist[k2 >> 16], 1u);
        atomicAdd(&g_hist[k3 >> 16], 1u);
    }
}

// ---------------- kernel 2: find level-1 threshold bin ----------------
__global__ void __launch_bounds__(1024) find_thr1() {
    __shared__ unsigned csum[1024];
    unsigned ssum = 0;
    int base = threadIdx.x * 64;
    for (int b = 0; b < 64; b++) ssum += g_hist[base + b];
    csum[threadIdx.x] = ssum;
    __syncthreads();
    if (threadIdx.x == 0) {
        unsigned acc = 0; int ch;
        for (ch = 1023; ch >= 0; ch--) {
            if (acc + csum[ch] >= (unsigned)KPRE) break;
            acc += csum[ch];
        }
        unsigned C1 = acc; int T = ch * 64;
        for (int b = 63; b >= 0; b--) {
            unsigned h = g_hist[ch*64 + b];
            if (C1 + h >= (unsigned)KPRE) { T = ch*64 + b; break; }
            C1 += h;
        }
        g_thr1 = T;
        g_k2 = KPRE - (int)C1;
    }
}

// ---------------- kernel 3: compact winners + boundary candidates (vectorized) ----------------
__global__ void compact1() {
    int p = blockIdx.x * blockDim.x + threadIdx.x;
    if (p >= NANCH/4) return;
    uint4 kv = *reinterpret_cast<const uint4*>(g_key + 4*(size_t)p);
    unsigned ks[4] = {kv.x, kv.y, kv.z, kv.w};
    int T = g_thr1;
#pragma unroll
    for (int j = 0; j < 4; j++) {
        unsigned key = ks[j];
        int bin = (int)(key >> 16);
        if (bin >= T) {
            int pos = 4*p + j;             // position in [a][HW] layout
            int a = pos / HW, s = pos - a*HW;
            int iorig = s*APL + a;
            if (bin > T) {
                int q = atomicAdd(&g_cntHi, 1);
                g_topk_idx[q] = iorig; g_topk_key[q] = key;
            } else {
                int q = atomicAdd(&g_candCnt, 1);
                if (q < CAND_CAP) { g_cand_key[q] = key; g_cand_idx[q] = iorig; }
            }
        }
    }
}

// ---------------- kernel 4: level-2 refinement + exact tie-break ----------------
__global__ void __launch_bounds__(1024) level2() {
    __shared__ unsigned csum[1024];
    __shared__ int sT2, sk3;
    int nc = min(g_candCnt, CAND_CAP);
    int k2 = g_k2;
    for (int t = threadIdx.x; t < nc; t += 1024)
        atomicAdd(&g_hist2[g_cand_key[t] & 0xFFFFu], 1u);
    __syncthreads();
    unsigned ssum = 0; int base = threadIdx.x * 64;
    for (int b = 0; b < 64; b++) ssum += g_hist2[base + b];
    csum[threadIdx.x] = ssum;
    __syncthreads();
    if (threadIdx.x == 0) {
        unsigned acc = 0; int ch;
        for (ch = 1023; ch >= 0; ch--) {
            if (acc + csum[ch] >= (unsigned)k2) break;
            acc += csum[ch];
        }
        unsigned C1 = acc; int T = ch * 64;
        for (int b = 63; b >= 0; b--) {
            unsigned h = g_hist2[ch*64 + b];
            if (C1 + h >= (unsigned)k2) { T = ch*64 + b; break; }
            C1 += h;
        }
        sT2 = T; sk3 = k2 - (int)C1;
    }
    __syncthreads();
    int T2 = sT2;
    for (int t = threadIdx.x; t < nc; t += 1024) {
        int low = (int)(g_cand_key[t] & 0xFFFFu);
        if (low > T2) {
            int p = atomicAdd(&g_cntHi, 1);
            g_topk_idx[p] = g_cand_idx[t];
            g_topk_key[p] = g_cand_key[t];
        } else if (low == T2) {
            int p = atomicAdd(&g_tieCnt, 1);
            if (p < TIE_CAP) g_tie[p] = g_cand_idx[t];
        }
    }
    __syncthreads();
    int m = min(g_tieCnt, TIE_CAP);
    int k3 = sk3;
    unsigned tie_key = ((unsigned)g_thr1 << 16) | (unsigned)T2;
    for (int t = threadIdx.x; t < m; t += 1024) {
        int idx = g_tie[t];
        int rank = 0;
        for (int u = 0; u < m; u++) rank += (g_tie[u] < idx) ? 1 : 0;
        if (rank < k3) {
            int p = atomicAdd(&g_cntHi, 1);
            g_topk_idx[p] = idx; g_topk_key[p] = tie_key;
        }
    }
}

// ---------------- kernel 4b: canonicalize top-k order (key desc, idx asc) ----------------
__global__ void __launch_bounds__(1024) sort_topk() {
    __shared__ unsigned long long sm[KPRE];
    for (int t = threadIdx.x; t < KPRE; t += 1024) {
        sm[t] = ((unsigned long long)g_topk_key[t] << 32) | (unsigned)(~(unsigned)g_topk_idx[t]);
    }
    __syncthreads();
    for (unsigned k = 2; k <= KPRE; k <<= 1) {
        for (unsigned j = k >> 1; j > 0; j >>= 1) {
            for (unsigned t = threadIdx.x; t < KPRE; t += 1024) {
                unsigned ixj = t ^ j;
                if (ixj > t) {
                    unsigned long long A = sm[t], B = sm[ixj];
                    if ((A < B) == ((t & k) == 0)) { sm[t] = B; sm[ixj] = A; }  // descending
                }
            }
            __syncthreads();
        }
    }
    for (int t = threadIdx.x; t < KPRE; t += 1024)
        g_topk_idx[t] = (int)(~(unsigned)(sm[t] & 0xFFFFFFFFu));
}

// ---------------- kernel 5: gather + decode the 4096 selected anchors ----------------
__global__ void decode_kernel(const float* __restrict__ cls, const float* __restrict__ bp,
                              const float* __restrict__ dirp, const float* __restrict__ priors) {
    int t = blockIdx.x * blockDim.x + threadIdx.x;
    if (t >= KPRE) return;
    int i = g_topk_idx[t];
    int s = i / APL, a = i - s * APL;
#pragma unroll
    for (int c = 0; c < 3; c++)
        g_sc[t*3 + c] = sigd(cls[(a*3 + c)*HW + s]);
    float dv0 = dirp[(a*2 + 0)*HW + s];
    float dv1 = dirp[(a*2 + 1)*HW + s];
    g_dirf[t] = (dv1 > dv0) ? 1.f : 0.f;

    float dl[7], an[7];
#pragma unroll
    for (int k = 0; k < 7; k++) {
        dl[k] = bp[(a*7 + k)*HW + s];
        an[k] = priors[(size_t)i*7 + k];
    }
    float za   = __fadd_rn(an[2], __fmul_rn(an[5], 0.5f));
    float diag = sqrtf(__fadd_rn(__fmul_rn(an[4], an[4]), __fmul_rn(an[3], an[3])));
    float xg = __fadd_rn(__fmul_rn(dl[0], diag), an[0]);
    float yg = __fadd_rn(__fmul_rn(dl[1], diag), an[1]);
    float zg = __fadd_rn(__fmul_rn(dl[2], an[5]), za);
    float wg = __fmul_rn(expf(dl[3]), an[3]);
    float lg = __fmul_rn(expf(dl[4]), an[4]);
    float hg = __fmul_rn(expf(dl[5]), an[5]);
    float rg = __fadd_rn(dl[6], an[6]);
    zg = __fsub_rn(zg, __fmul_rn(hg, 0.5f));
    g_box[t*7+0]=xg; g_box[t*7+1]=yg; g_box[t*7+2]=zg;
    g_box[t*7+3]=wg; g_box[t*7+4]=lg; g_box[t*7+5]=hg; g_box[t*7+6]=rg;
    g_xyxy[t] = make_float4(__fsub_rn(xg, __fmul_rn(wg, 0.5f)),
                            __fsub_rn(yg, __fmul_rn(lg, 0.5f)),
                            __fadd_rn(xg, __fmul_rn(wg, 0.5f)),
                            __fadd_rn(yg, __fmul_rn(lg, 0.5f)));
}

// ---------------- kernel 6: per-class bitonic sort (score desc, topk-pos asc) ----------------
__global__ void __launch_bounds__(1024) sort_class() {
    int c = blockIdx.x;
    __shared__ unsigned long long sm[KPRE];
    for (int t = threadIdx.x; t < KPRE; t += 1024) {
        float sc = g_sc[t*3 + c];
        sm[t] = ((unsigned long long)__float_as_uint(sc) << 32) | (unsigned)(~(unsigned)t);
    }
    __syncthreads();
    for (unsigned k = 2; k <= KPRE; k <<= 1) {
        for (unsigned j = k >> 1; j > 0; j >>= 1) {
            for (unsigned t = threadIdx.x; t < KPRE; t += 1024) {
                unsigned ixj = t ^ j;
                if (ixj > t) {
                    unsigned long long A = sm[t], B = sm[ixj];
                    if ((A < B) == ((t & k) == 0)) { sm[t] = B; sm[ixj] = A; }
                }
            }
            __syncthreads();
        }
    }
    for (int t = threadIdx.x; t < KPRE; t += 1024) {
        unsigned long long key = sm[t];
        int slot = (int)(~(unsigned)(key & 0xFFFFFFFFu));
        g_sorted_slot[c*KPRE + t] = slot;
        g_sorted_score[c*KPRE + t] = __uint_as_float((unsigned)(key >> 32));
        g_sxy[c*KPRE + t] = g_xyxy[slot];
    }
}

// ---------------- kernel 7: greedy NMS — bitmap pick + register separation precheck ----------------
__global__ void __launch_bounds__(1024) nms_reduce() {
    int c = blockIdx.x;
    int tid = threadIdx.x;
    int wid = tid >> 5, lane = tid & 31;
    __shared__ unsigned long long remv[64];   // removed OR invalid, indexed by rank
    __shared__ int s_i;
    __shared__ float s_ref[8];                // x1,y1,x2,y2, sx,dx3, sy,dy3
    __shared__ int s_keptrank[MAXN];

    // register-resident boxes: thread owns sorted ranks {tid, tid+1024, tid+2048, tid+3072}
    float4 bx[4];
    float sxk[4], dxk[4], syk[4], dyk[4];     // x1+x2, x2-x1, y1+y2, y2-y1
    bool alive[4];
#pragma unroll
    for (int k = 0; k < 4; k++) {
        float4 b = g_sxy[c*KPRE + tid + k*1024];
        bx[k] = b;
        sxk[k] = b.x + b.z;  dxk[k] = b.z - b.x;
        syk[k] = b.y + b.w;  dyk[k] = b.w - b.y;
        alive[k] = true;
    }
    if (tid < 64) remv[tid] = 0ull;
    __syncthreads();
    // mark invalid (score <= thr) as removed, via per-warp ballots (distinct words)
#pragma unroll
    for (int k = 0; k < 4; k++) {
        float sc = g_sorted_score[c*KPRE + tid + k*1024];
        unsigned bad = __ballot_sync(0xFFFFFFFFu, !(sc > SCORE_THR));
        if (lane == 0 && bad) {
            int j0 = k*1024 + wid*32;
            atomicOr(&remv[j0 >> 6], (unsigned long long)bad << (j0 & 63));
        }
    }
    __syncthreads();

    int cnt = 0;
    int wd0 = 0;   // thread0 only
    while (true) {
        if (tid == 0) {
            int found = -1;
            for (int wd = wd0; wd < 64; wd++) {
                unsigned long long avail = ~remv[wd];
                if (avail) { found = wd*64 + __ffsll((long long)avail) - 1; wd0 = wd; break; }
            }
            s_i = found;
            if (found >= 0) {
                remv[found >> 6] |= 1ull << (found & 63);
                s_keptrank[cnt] = found;
            }
        }
        __syncthreads();                       // bar1: s_i visible
        int i = s_i;
        if (i < 0) break;
        if (tid == (i & 1023)) {               // owner publishes from registers
            int k = i >> 10;
            s_ref[0] = bx[k].x; s_ref[1] = bx[k].y;
            s_ref[2] = bx[k].z; s_ref[3] = bx[k].w;
            s_ref[4] = sxk[k];  s_ref[5] = dxk[k] + 3.0f;
            s_ref[6] = syk[k];  s_ref[7] = dyk[k] + 3.0f;
            alive[k] = false;
        }
        __syncthreads();                       // bar2: s_ref visible
        // cheap conservative separation test (registers only)
        float rsx = s_ref[4], rdx3 = s_ref[5], rsy = s_ref[6], rdy3 = s_ref[7];
        bool pass[4]; bool anyp = false;
#pragma unroll
        for (int k = 0; k < 4; k++) {
            int j = tid + k*1024;
            bool p = alive[k] && (j > i)
                  && (fabsf(sxk[k] - rsx) < dxk[k] + rdx3)
                  && (fabsf(syk[k] - rsy) < dyk[k] + rdy3);
            pass[k] = p; anyp |= p;
        }
        if (__any_sync(0xFFFFFFFFu, anyp)) {   // rare path: exact IoU (bit-identical to ref)
            float rx1 = s_ref[0], ry1 = s_ref[1], rx2 = s_ref[2], ry2 = s_ref[3];
            float ra = area_rn(rx1, ry1, rx2, ry2);
#pragma unroll
            for (int k = 0; k < 4; k++) {
                if (pass[k]) {
                    int j = tid + k*1024;
                    float xx1 = fmaxf(rx1, bx[k].x);
                    float yy1 = fmaxf(ry1, bx[k].y);
                    float xx2 = fminf(rx2, bx[k].z);
                    float yy2 = fminf(ry2, bx[k].w);
                    float w  = __fadd_rn(__fsub_rn(xx2, xx1), 1.f);
                    float h2 = __fadd_rn(__fsub_rn(yy2, yy1), 1.f);
                    if (w > 0.f && h2 > 0.f) {
                        float inter = __fmul_rn(w, h2);
                        float ark = area_rn(bx[k].x, bx[k].y, bx[k].z, bx[k].w);
                        float den = __fsub_rn(__fadd_rn(ra, ark), inter);
                        if (__fdiv_rn(inter, den) > NMS_THR) {
                            alive[k] = false;
                            atomicOr(&remv[j >> 6], 1ull << (j & 63));
                        }
                    }
                }
            }
        }
        __syncthreads();                       // bar3: remv updates visible to thread0
        cnt++;
        if (cnt >= MAXN) break;
    }
    // materialize kept list (gathers out of the serial loop)
    for (int r = tid; r < cnt; r += 1024) {
        int rk = s_keptrank[r];
        g_kept_slot[c*MAXN + r]  = g_sorted_slot[c*KPRE + rk];
        g_kept_score[c*MAXN + r] = g_sorted_score[c*KPRE + rk];
    }
    if (tid == 0) g_kept_cnt[c] = cnt;
}

// ---------------- kernel 8: merge + final top-500 + output ----------------
__global__ void __launch_bounds__(1024) final_merge(float* __restrict__ out) {
    __shared__ unsigned long long sm[2048];
    for (int t = threadIdx.x; t < 2048; t += 1024) {
        unsigned long long key = 0ull;
        if (t < 3*MAXN) {
            int c = t / MAXN, pos = t % MAXN;
            if (pos < g_kept_cnt[c]) {
                float sc = g_kept_score[c*MAXN + pos];
                unsigned flat = (unsigned)(c*KPRE + pos);
                key = ((unsigned long long)__float_as_uint(sc) << 32) | (unsigned)(~flat);
            }
        }
        sm[t] = key;
    }
    __syncthreads();
    for (unsigned k = 2; k <= 2048; k <<= 1) {
        for (unsigned j = k >> 1; j > 0; j >>= 1) {
            for (unsigned t = threadIdx.x; t < 2048; t += 1024) {
                unsigned ixj = t ^ j;
                if (ixj > t) {
                    unsigned long long A = sm[t], B = sm[ixj];
                    if ((A < B) == ((t & k) == 0)) { sm[t] = B; sm[ixj] = A; }
                }
            }
            __syncthreads();
        }
    }
    for (int r = threadIdx.x; r < MAXN; r += 1024) {
        unsigned long long key = sm[r];
        if (key != 0ull) {
            float score = __uint_as_float((unsigned)(key >> 32));
            unsigned flat = ~(unsigned)(key & 0xFFFFFFFFu);
            int c = (int)(flat >> 12);
            int pos = (int)(flat & 4095u);
            int slot = g_kept_slot[c*MAXN + pos];
            float b[7];
#pragma unroll
            for (int k = 0; k < 7; k++) b[k] = g_box[slot*7 + k];
            float rr = b[6];
            float dir_rot = __fsub_rn(__fadd_rn(rr, PIH_F),
                                      __fmul_rn(floorf(__fadd_rn(rr, 0.5f)), PI_F));
            b[6] = __fadd_rn(__fsub_rn(dir_rot, PIH_F), __fmul_rn(PI_F, g_dirf[slot]));
#pragma unroll
            for (int k = 0; k < 7; k++) out[r*7 + k] = b[k];
            out[7*MAXN + r] = score;
            out[8*MAXN + r] = (float)c;
        } else {
#pragma unroll
            for (int k = 0; k < 7; k++) out[r*7 + k] = 0.f;
            out[7*MAXN + r] = 0.f;
            out[8*MAXN + r] = -1.f;
        }
    }
}

// ---------------- launch ----------------
extern "C" void kernel_launch(void* const* d_in, const int* in_sizes, int n_in,
                              void* d_out, int out_size) {
    const float* cls    = (const float*)d_in[0];
    const float* bp     = (const float*)d_in[1];
    const float* dirp   = (const float*)d_in[2];
    const float* priors = (const float*)d_in[3];
    float* out = (float*)d_out;

    zero_kernel<<<256, 256>>>();
    score_hist<<<(HW/4 + 255) / 256, 256>>>(cls);
    find_thr1<<<1, 1024>>>();
    compact1<<<(NANCH/4 + 255) / 256, 256>>>();
    level2<<<1, 1024>>>();
    sort_topk<<<1, 1024>>>();
    decode_kernel<<<(KPRE + 255) / 256, 256>>>(cls, bp, dirp, priors);
    sort_class<<<3, 1024>>>();
    nms_reduce<<<3, 1024>>>();
    final_merge<<<1, 1024>>>(out);
}

// round 9
// speedup vs baseline: 1.5914x; 1.2555x over previous
#include <cuda_runtime.h>
#include <cuda_fp16.h>
#include <math.h>

#define HH 496
#define WW 432
#define HW (HH*WW)            // 214272
#define APL 6
#define NANCH (HW*APL)        // 1285632
#define KPRE 4096
#define MAXN 500
#define SCORE_THR 0.1f
#define NMS_THR 0.5f
#define CAND_CAP (1<<18)
#define TIE_CAP 4096
#define PI_F 3.14159265358979323846f
#define PIH_F 1.57079632679489661923f

// NMS spatial-grid constants
#define CSX 35
#define CSY 40
#define NCELL (CSX*CSY)       // 1400
#define EDGE_CAP 16384
#define DEG_CAP 64

// dynamic smem layout (bytes)
#define OFF_PC        0                      // uint2[4096]        32768
#define OFF_CLIST     32768                  // u16[4096]           8192
#define OFF_OFFS      40960                  // u16[4100]           8200 (pad)
#define OFF_EDGES     49168                  // u16[EDGE_CAP]      32768
#define OFF_CCNT      81936                  // int[NCELL]          5600
#define OFF_CSTART    87536                  // int[NCELL+1]        5604 (pad)
#define OFF_KEEP      93152                  // u64[64]              512
#define OFF_KEPT      93664                  // int[MAXN]           2000
#define OFF_MISC      95664                  // int[96]              384
#define DSM_TOTAL     96256

// ---------------- device scratch (static, no allocations) ----------------
__device__ unsigned g_key[NANCH];            // layout [a][HW]
__device__ unsigned g_hist[65536];
__device__ unsigned g_hist2[65536];
__device__ int g_cntHi;
__device__ int g_candCnt;
__device__ int g_tieCnt;
__device__ int g_thr1;
__device__ int g_k2;
__device__ unsigned g_cand_key[CAND_CAP];
__device__ int      g_cand_idx[CAND_CAP];
__device__ int      g_tie[TIE_CAP];
__device__ int      g_topk_idx[KPRE];        // original flat index s*APL+a
__device__ unsigned g_topk_key[KPRE];
__device__ float    g_sc[KPRE*3];
__device__ float    g_dirf[KPRE];
__device__ float    g_box[KPRE*7];
__device__ float4   g_xyxy[KPRE];
__device__ int      g_sorted_slot[3*KPRE];
__device__ float    g_sorted_score[3*KPRE];
__device__ float4   g_sxy[3*KPRE];
__device__ int      g_kept_slot[3*MAXN];
__device__ float    g_kept_score[3*MAXN];
__device__ int      g_kept_cnt[3];

__device__ __forceinline__ float sigd(float x) {
    // double-rounded sigmoid: matches fp32 reference sigmoid to <=1ulp
    return (float)(1.0 / (1.0 + exp(-(double)x)));
}

__device__ __forceinline__ unsigned mono_key(float m) {
    // order-preserving map fp32 -> u32 (sigmoid is monotone in the logit)
    unsigned b = __float_as_uint(m);
    return (b & 0x80000000u) ? ~b : (b | 0x80000000u);
}

__device__ __forceinline__ float area_rn(float x1, float y1, float x2, float y2) {
    return __fmul_rn(__fadd_rn(__fsub_rn(x2, x1), 1.f),
                     __fadd_rn(__fsub_rn(y2, y1), 1.f));
}

// ---------------- kernel 0: zero scratch ----------------
__global__ void zero_kernel() {
    int t = blockIdx.x * blockDim.x + threadIdx.x;
    if (t < 65536) { g_hist[t] = 0u; g_hist2[t] = 0u; }
    if (t == 0) { g_cntHi = 0; g_candCnt = 0; g_tieCnt = 0; }
}

// ---------------- kernel 1: per-anchor max-logit key + histogram (vectorized) ----------------
__global__ void score_hist(const float* __restrict__ cls) {
    int t = blockIdx.x * blockDim.x + threadIdx.x;
    if (t >= HW/4) return;
    int s = t * 4;
#pragma unroll
    for (int a = 0; a < APL; a++) {
        const float4 v0 = *reinterpret_cast<const float4*>(cls + (size_t)(a*3+0)*HW + s);
        const float4 v1 = *reinterpret_cast<const float4*>(cls + (size_t)(a*3+1)*HW + s);
        const float4 v2 = *reinterpret_cast<const float4*>(cls + (size_t)(a*3+2)*HW + s);
        unsigned k0 = mono_key(fmaxf(fmaxf(v0.x, v1.x), v2.x));
        unsigned k1 = mono_key(fmaxf(fmaxf(v0.y, v1.y), v2.y));
        unsigned k2 = mono_key(fmaxf(fmaxf(v0.z, v1.z), v2.z));
        unsigned k3 = mono_key(fmaxf(fmaxf(v0.w, v1.w), v2.w));
        *reinterpret_cast<uint4*>(g_key + (size_t)a*HW + s) = make_uint4(k0, k1, k2, k3);
        atomicAdd(&g_hist[k0 >> 16], 1u);
        atomicAdd(&g_hist[k1 >> 16], 1u);
        atomicAdd(&g_hist[k2 >> 16], 1u);
        atomicAdd(&g_hist[k3 >> 16], 1u);
    }
}

// ---------------- kernel 2: find level-1 threshold bin ----------------
__global__ void __launch_bounds__(1024) find_thr1() {
    __shared__ unsigned csum[1024];
    unsigned ssum = 0;
    int base = threadIdx.x * 64;
    for (int b = 0; b < 64; b++) ssum += g_hist[base + b];
    csum[threadIdx.x] = ssum;
    __syncthreads();
    if (threadIdx.x == 0) {
        unsigned acc = 0; int ch;
        for (ch = 1023; ch >= 0; ch--) {
            if (acc + csum[ch] >= (unsigned)KPRE) break;
            acc += csum[ch];
        }
        unsigned C1 = acc; int T = ch * 64;
        for (int b = 63; b >= 0; b--) {
            unsigned h = g_hist[ch*64 + b];
            if (C1 + h >= (unsigned)KPRE) { T = ch*64 + b; break; }
            C1 += h;
        }
        g_thr1 = T;
        g_k2 = KPRE - (int)C1;
    }
}

// ---------------- kernel 3: compact winners + boundary candidates (vectorized) ----------------
__global__ void compact1() {
    int p = blockIdx.x * blockDim.x + threadIdx.x;
    if (p >= NANCH/4) return;
    uint4 kv = *reinterpret_cast<const uint4*>(g_key + 4*(size_t)p);
    unsigned ks[4] = {kv.x, kv.y, kv.z, kv.w};
    int T = g_thr1;
#pragma unroll
    for (int j = 0; j < 4; j++) {
        unsigned key = ks[j];
        int bin = (int)(key >> 16);
        if (bin >= T) {
            int pos = 4*p + j;             // position in [a][HW] layout
            int a = pos / HW, s = pos - a*HW;
            int iorig = s*APL + a;
            if (bin > T) {
                int q = atomicAdd(&g_cntHi, 1);
                g_topk_idx[q] = iorig; g_topk_key[q] = key;
            } else {
                int q = atomicAdd(&g_candCnt, 1);
                if (q < CAND_CAP) { g_cand_key[q] = key; g_cand_idx[q] = iorig; }
            }
        }
    }
}

// ---------------- kernel 4: level-2 refinement + exact tie-break ----------------
__global__ void __launch_bounds__(1024) level2() {
    __shared__ unsigned csum[1024];
    __shared__ int sT2, sk3;
    int nc = min(g_candCnt, CAND_CAP);
    int k2 = g_k2;
    for (int t = threadIdx.x; t < nc; t += 1024)
        atomicAdd(&g_hist2[g_cand_key[t] & 0xFFFFu], 1u);
    __syncthreads();
    unsigned ssum = 0; int base = threadIdx.x * 64;
    for (int b = 0; b < 64; b++) ssum += g_hist2[base + b];
    csum[threadIdx.x] = ssum;
    __syncthreads();
    if (threadIdx.x == 0) {
        unsigned acc = 0; int ch;
        for (ch = 1023; ch >= 0; ch--) {
            if (acc + csum[ch] >= (unsigned)k2) break;
            acc += csum[ch];
        }
        unsigned C1 = acc; int T = ch * 64;
        for (int b = 63; b >= 0; b--) {
            unsigned h = g_hist2[ch*64 + b];
            if (C1 + h >= (unsigned)k2) { T = ch*64 + b; break; }
            C1 += h;
        }
        sT2 = T; sk3 = k2 - (int)C1;
    }
    __syncthreads();
    int T2 = sT2;
    for (int t = threadIdx.x; t < nc; t += 1024) {
        int low = (int)(g_cand_key[t] & 0xFFFFu);
        if (low > T2) {
            int p = atomicAdd(&g_cntHi, 1);
            g_topk_idx[p] = g_cand_idx[t];
            g_topk_key[p] = g_cand_key[t];
        } else if (low == T2) {
            int p = atomicAdd(&g_tieCnt, 1);
            if (p < TIE_CAP) g_tie[p] = g_cand_idx[t];
        }
    }
    __syncthreads();
    int m = min(g_tieCnt, TIE_CAP);
    int k3 = sk3;
    unsigned tie_key = ((unsigned)g_thr1 << 16) | (unsigned)T2;
    for (int t = threadIdx.x; t < m; t += 1024) {
        int idx = g_tie[t];
        int rank = 0;
        for (int u = 0; u < m; u++) rank += (g_tie[u] < idx) ? 1 : 0;
        if (rank < k3) {
            int p = atomicAdd(&g_cntHi, 1);
            g_topk_idx[p] = idx; g_topk_key[p] = tie_key;
        }
    }
}

// ---------------- kernel 4b: canonicalize top-k order (key desc, idx asc) ----------------
__global__ void __launch_bounds__(1024) sort_topk() {
    __shared__ unsigned long long sm[KPRE];
    for (int t = threadIdx.x; t < KPRE; t += 1024) {
        sm[t] = ((unsigned long long)g_topk_key[t] << 32) | (unsigned)(~(unsigned)g_topk_idx[t]);
    }
    __syncthreads();
    for (unsigned k = 2; k <= KPRE; k <<= 1) {
        for (unsigned j = k >> 1; j > 0; j >>= 1) {
            for (unsigned t = threadIdx.x; t < KPRE; t += 1024) {
                unsigned ixj = t ^ j;
                if (ixj > t) {
                    unsigned long long A = sm[t], B = sm[ixj];
                    if ((A < B) == ((t & k) == 0)) { sm[t] = B; sm[ixj] = A; }  // descending
                }
            }
            __syncthreads();
        }
    }
    for (int t = threadIdx.x; t < KPRE; t += 1024)
        g_topk_idx[t] = (int)(~(unsigned)(sm[t] & 0xFFFFFFFFu));
}

// ---------------- kernel 5: gather + decode the 4096 selected anchors ----------------
__global__ void decode_kernel(const float* __restrict__ cls, const float* __restrict__ bp,
                              const float* __restrict__ dirp, const float* __restrict__ priors) {
    int t = blockIdx.x * blockDim.x + threadIdx.x;
    if (t >= KPRE) return;
    int i = g_topk_idx[t];
    int s = i / APL, a = i - s * APL;
#pragma unroll
    for (int c = 0; c < 3; c++)
        g_sc[t*3 + c] = sigd(cls[(a*3 + c)*HW + s]);
    float dv0 = dirp[(a*2 + 0)*HW + s];
    float dv1 = dirp[(a*2 + 1)*HW + s];
    g_dirf[t] = (dv1 > dv0) ? 1.f : 0.f;

    float dl[7], an[7];
#pragma unroll
    for (int k = 0; k < 7; k++) {
        dl[k] = bp[(a*7 + k)*HW + s];
        an[k] = priors[(size_t)i*7 + k];
    }
    float za   = __fadd_rn(an[2], __fmul_rn(an[5], 0.5f));
    float diag = sqrtf(__fadd_rn(__fmul_rn(an[4], an[4]), __fmul_rn(an[3], an[3])));
    float xg = __fadd_rn(__fmul_rn(dl[0], diag), an[0]);
    float yg = __fadd_rn(__fmul_rn(dl[1], diag), an[1]);
    float zg = __fadd_rn(__fmul_rn(dl[2], an[5]), za);
    float wg = __fmul_rn(expf(dl[3]), an[3]);
    float lg = __fmul_rn(expf(dl[4]), an[4]);
    float hg = __fmul_rn(expf(dl[5]), an[5]);
    float rg = __fadd_rn(dl[6], an[6]);
    zg = __fsub_rn(zg, __fmul_rn(hg, 0.5f));
    g_box[t*7+0]=xg; g_box[t*7+1]=yg; g_box[t*7+2]=zg;
    g_box[t*7+3]=wg; g_box[t*7+4]=lg; g_box[t*7+5]=hg; g_box[t*7+6]=rg;
    g_xyxy[t] = make_float4(__fsub_rn(xg, __fmul_rn(wg, 0.5f)),
                            __fsub_rn(yg, __fmul_rn(lg, 0.5f)),
                            __fadd_rn(xg, __fmul_rn(wg, 0.5f)),
                            __fadd_rn(yg, __fmul_rn(lg, 0.5f)));
}

// ---------------- kernel 6: per-class bitonic sort (score desc, topk-pos asc) ----------------
__global__ void __launch_bounds__(1024) sort_class() {
    int c = blockIdx.x;
    __shared__ unsigned long long sm[KPRE];
    for (int t = threadIdx.x; t < KPRE; t += 1024) {
        float sc = g_sc[t*3 + c];
        sm[t] = ((unsigned long long)__float_as_uint(sc) << 32) | (unsigned)(~(unsigned)t);
    }
    __syncthreads();
    for (unsigned k = 2; k <= KPRE; k <<= 1) {
        for (unsigned j = k >> 1; j > 0; j >>= 1) {
            for (unsigned t = threadIdx.x; t < KPRE; t += 1024) {
                unsigned ixj = t ^ j;
                if (ixj > t) {
                    unsigned long long A = sm[t], B = sm[ixj];
                    if ((A < B) == ((t & k) == 0)) { sm[t] = B; sm[ixj] = A; }
                }
            }
            __syncthreads();
        }
    }
    for (int t = threadIdx.x; t < KPRE; t += 1024) {
        unsigned long long key = sm[t];
        int slot = (int)(~(unsigned)(key & 0xFFFFFFFFu));
        g_sorted_slot[c*KPRE + t] = slot;
        g_sorted_score[c*KPRE + t] = __uint_as_float((unsigned)(key >> 32));
        g_sxy[c*KPRE + t] = g_xyxy[slot];
    }
}

// ---------------- kernel 7: NMS via sparse suppression edges (no serial barrier loop) ----------------
__global__ void __launch_bounds__(1024) nms_reduce() {
    extern __shared__ char dsm[];
    uint2*              s_pc     = (uint2*)(dsm + OFF_PC);
    unsigned short*     s_clist  = (unsigned short*)(dsm + OFF_CLIST);
    unsigned short*     s_offs   = (unsigned short*)(dsm + OFF_OFFS);
    unsigned short*     s_edges  = (unsigned short*)(dsm + OFF_EDGES);
    int*                s_ccnt   = (int*)(dsm + OFF_CCNT);
    int*                s_cstart = (int*)(dsm + OFF_CSTART);
    unsigned long long* s_keep   = (unsigned long long*)(dsm + OFF_KEEP);
    int*                s_kept   = (int*)(dsm + OFF_KEPT);
    int*                s_misc   = (int*)(dsm + OFF_MISC);
    float*              s_miscf  = (float*)(dsm + OFF_MISC);

    int c = blockIdx.x, tid = threadIdx.x;
    int lane = tid & 31, wid = tid >> 5;
    const unsigned FULL = 0xFFFFFFFFu;

    // --- load 4 contiguous-by-rank boxes; publish packed half data; bin ---
    float4 bx[4]; float cxr[4], cyr[4], hxr[4], hyr[4];
    int cel[4], pos[4];
    float mhx = 0.f, mhy = 0.f;
#pragma unroll
    for (int k = 0; k < 4; k++) {
        int r = 4*tid + k;
        float4 b = g_sxy[c*KPRE + r];
        bx[k] = b;
        cxr[k] = (b.x + b.z) * 0.5f;  cyr[k] = (b.y + b.w) * 0.5f;
        hxr[k] = (b.z - b.x) * 0.5f;  hyr[k] = (b.w - b.y) * 0.5f;
        mhx = fmaxf(mhx, hxr[k]);     mhy = fmaxf(mhy, hyr[k]);
        int ix = min(CSX-1, max(0, (int)(cxr[k]*0.5f)));
        int iy = min(CSY-1, max(0, (int)((cyr[k]+40.f)*0.5f)));
        cel[k] = iy*CSX + ix;
        __half2 pcc = __floats2half2_rn(cxr[k], cyr[k]);
        __half2 phh = __floats2half2_rn(hxr[k], hyr[k]);
        uint2 u;
        u.x = *reinterpret_cast<unsigned*>(&pcc);
        u.y = *reinterpret_cast<unsigned*>(&phh);
        s_pc[r] = u;
    }
    for (int t = tid; t < NCELL; t += 1024) s_ccnt[t] = 0;
    if (tid == 0) s_misc[73] = 0;    // overflow flag
#pragma unroll
    for (int o = 16; o > 0; o >>= 1) {
        mhx = fmaxf(mhx, __shfl_xor_sync(FULL, mhx, o));
        mhy = fmaxf(mhy, __shfl_xor_sync(FULL, mhy, o));
    }
    __syncthreads();
    if (lane == 0) { s_miscf[wid] = mhx; s_miscf[40 + wid] = mhy; }
    __syncthreads();
    if (tid == 0) {
        float a = 0.f, b2 = 0.f;
        for (int w = 0; w < 32; w++) { a = fmaxf(a, s_miscf[w]); b2 = fmaxf(b2, s_miscf[40+w]); }
        s_miscf[84] = a; s_miscf[85] = b2;
    }
#pragma unroll
    for (int k = 0; k < 4; k++) pos[k] = atomicAdd(&s_ccnt[cel[k]], 1);
    __syncthreads();

    // --- exclusive scan cell counts -> cell starts (2 cells per thread) ---
    int i0 = tid*2, i1 = tid*2 + 1;
    int v0 = (i0 < NCELL) ? s_ccnt[i0] : 0;
    int v1 = (i1 < NCELL) ? s_ccnt[i1] : 0;
    int ts = v0 + v1, xs = ts;
#pragma unroll
    for (int o = 1; o < 32; o <<= 1) { int y = __shfl_up_sync(FULL, xs, o); if (lane >= o) xs += y; }
    if (lane == 31) s_misc[wid] = xs;
    __syncthreads();
    if (wid == 0) {
        int w = s_misc[lane];
#pragma unroll
        for (int o = 1; o < 32; o <<= 1) { int y = __shfl_up_sync(FULL, w, o); if (lane >= o) w += y; }
        s_misc[lane] = w;
    }
    __syncthreads();
    int cbase = (wid ? s_misc[wid-1] : 0) + (xs - ts);
    if (i0 < NCELL) s_cstart[i0] = cbase;
    if (i1 < NCELL) s_cstart[i1] = cbase + v0;
    if (tid == 1023) s_cstart[NCELL] = cbase + ts;
    __syncthreads();
#pragma unroll
    for (int k = 0; k < 4; k++)
        s_clist[s_cstart[cel[k]] + pos[k]] = (unsigned short)(4*tid + k);
    __syncthreads();

    // --- edge scan: suppressors i<r with exact IoU > thr ---
    float MHX = s_miscf[84], MHY = s_miscf[85];
    int nrx = min(CSX-1, (int)((2.f*MHX + 1.6f)*0.5f) + 1);
    int nry = min(CSY-1, (int)((2.f*MHY + 1.6f)*0.5f) + 1);

    unsigned short lbuf[4][DEG_CAP];
    int deg[4];
    bool over = false;
#pragma unroll
    for (int k = 0; k < 4; k++) {
        deg[k] = 0;
        int r = 4*tid + k;
        int ixc = cel[k] % CSX, iyc = cel[k] / CSX;
        float mycx = cxr[k], mycy = cyr[k], myhx = hxr[k], myhy = hyr[k];
        float aj = area_rn(bx[k].x, bx[k].y, bx[k].z, bx[k].w);
        int y0 = max(0, iyc-nry), y1 = min(CSY-1, iyc+nry);
        int x0 = max(0, ixc-nrx), x1 = min(CSX-1, ixc+nrx);
        for (int iy = y0; iy <= y1; iy++) {
            int rowb = iy*CSX;
            int qs = s_cstart[rowb + x0];
            int qe = s_cstart[rowb + x1 + 1];
            for (int q = qs; q < qe; q++) {
                int i = s_clist[q];
                if (i >= r) continue;
                uint2 u = s_pc[i];
                __half2 hcc = *reinterpret_cast<__half2*>(&u.x);
                __half2 hhh = *reinterpret_cast<__half2*>(&u.y);
                float2 cc = __half22float2(hcc);
                float2 hh = __half22float2(hhh);
                if (fabsf(cc.x - mycx) < hh.x + myhx + 1.3f &&
                    fabsf(cc.y - mycy) < hh.y + myhy + 1.3f) {
                    float4 ob = __ldg(&g_sxy[c*KPRE + i]);
                    float xx1 = fmaxf(ob.x, bx[k].x), yy1 = fmaxf(ob.y, bx[k].y);
                    float xx2 = fminf(ob.z, bx[k].z), yy2 = fminf(ob.w, bx[k].w);
                    float w  = __fadd_rn(__fsub_rn(xx2, xx1), 1.f);
                    float h2 = __fadd_rn(__fsub_rn(yy2, yy1), 1.f);
                    if (w > 0.f && h2 > 0.f) {
                        float inter = __fmul_rn(w, h2);
                        float ai = area_rn(ob.x, ob.y, ob.z, ob.w);
                        float den = __fsub_rn(__fadd_rn(ai, aj), inter);
                        if (__fdiv_rn(inter, den) > NMS_THR) {
                            if (deg[k] < DEG_CAP) lbuf[k][deg[k]] = (unsigned short)i;
                            deg[k]++;
                        }
                    }
                }
            }
        }
        if (deg[k] > DEG_CAP) over = true;
    }

    // --- CSR offsets via block scan; overflow -> fallback ---
    int tsum = deg[0] + deg[1] + deg[2] + deg[3];
    int xe = tsum;
#pragma unroll
    for (int o = 1; o < 32; o <<= 1) { int y = __shfl_up_sync(FULL, xe, o); if (lane >= o) xe += y; }
    if (lane == 31) s_misc[wid] = xe;
    if (over) s_misc[73] = 1;
    __syncthreads();
    if (wid == 0) {
        int w = s_misc[lane];
#pragma unroll
        for (int o = 1; o < 32; o <<= 1) { int y = __shfl_up_sync(FULL, w, o); if (lane >= o) w += y; }
        s_misc[lane] = w;
        if (lane == 31 && w > EDGE_CAP) s_misc[73] = 1;
    }
    __syncthreads();
    bool flag = (s_misc[73] != 0);
    if (!flag) {
        int o2 = (wid ? s_misc[wid-1] : 0) + (xe - tsum);
#pragma unroll
        for (int k = 0; k < 4; k++) {
            s_offs[4*tid + k] = (unsigned short)o2;
            for (int e = 0; e < deg[k]; e++) s_edges[o2 + e] = lbuf[k][e];
            o2 += deg[k];
        }
        if (tid == 1023) s_offs[KPRE] = (unsigned short)o2;
    }
    // valid bits by rank
    if (tid < 64) {
        unsigned long long wv = 0ull;
        for (int b = 0; b < 64; b++)
            if (g_sorted_score[c*KPRE + tid*64 + b] > SCORE_THR) wv |= 1ull << b;
        s_keep[tid] = wv;
    }
    __syncthreads();

    if (!flag) {
        // --- serial resolve over sparse edges (one thread, no barriers) ---
        if (tid == 0) {
            int kcnt = 0;
            for (int wd = 0; wd < 64 && kcnt < MAXN; wd++) {
                unsigned long long w = s_keep[wd];
                while (w) {
                    int b = __ffsll((long long)w) - 1; w &= w - 1;
                    int j = wd*64 + b;
                    int o = s_offs[j];
                    int d = (int)s_offs[j+1] - o;
                    bool dead = false;
                    for (int e = 0; e < d; e++) {
                        int i = s_edges[o + e];
                        if ((s_keep[i >> 6] >> (i & 63)) & 1ull) { dead = true; break; }
                    }
                    if (dead) s_keep[wd] &= ~(1ull << b);
                    else { s_kept[kcnt] = j; if (++kcnt >= MAXN) break; }
                }
            }
            s_misc[74] = kcnt;
        }
        __syncthreads();
        int kc = s_misc[74];
        for (int r2 = tid; r2 < kc; r2 += 1024) {
            int rk = s_kept[r2];
            g_kept_slot[c*MAXN + r2]  = g_sorted_slot[c*KPRE + rk];
            g_kept_score[c*MAXN + r2] = g_sorted_score[c*KPRE + rk];
        }
        if (tid == 0) g_kept_cnt[c] = kc;
        return;
    }

    // --- FALLBACK: iterative greedy loop (rare; guaranteed-correct) ---
    if (tid < 64) s_keep[tid] = ~s_keep[tid];      // now = removed bits
    __syncthreads();
    float* s_ref = &s_miscf[76];
    int cnt = 0, wd0 = 0;
    while (true) {
        if (tid == 0) {
            int found = -1;
            for (int wd = wd0; wd < 64; wd++) {
                unsigned long long avail = ~s_keep[wd];
                if (avail) { found = wd*64 + __ffsll((long long)avail) - 1; wd0 = wd; break; }
            }
            s_misc[75] = found;
            if (found >= 0) {
                s_keep[found >> 6] |= 1ull << (found & 63);
                s_kept[cnt] = found;
            }
        }
        __syncthreads();
        int i = s_misc[75];
        if (i < 0) break;
        if (tid == (i >> 2)) {
            int k = i & 3;
            s_ref[0] = bx[k].x; s_ref[1] = bx[k].y; s_ref[2] = bx[k].z; s_ref[3] = bx[k].w;
        }
        __syncthreads();
        float rx1 = s_ref[0], ry1 = s_ref[1], rx2 = s_ref[2], ry2 = s_ref[3];
        float ra = area_rn(rx1, ry1, rx2, ry2);
#pragma unroll
        for (int k = 0; k < 4; k++) {
            int j = 4*tid + k;
            if (j > i && !((s_keep[j >> 6] >> (j & 63)) & 1ull)) {
                float xx1 = fmaxf(rx1, bx[k].x), yy1 = fmaxf(ry1, bx[k].y);
                float xx2 = fminf(rx2, bx[k].z), yy2 = fminf(ry2, bx[k].w);
                float w  = __fadd_rn(__fsub_rn(xx2, xx1), 1.f);
                float h2 = __fadd_rn(__fsub_rn(yy2, yy1), 1.f);
                if (w > 0.f && h2 > 0.f) {
                    float inter = __fmul_rn(w, h2);
                    float ark = area_rn(bx[k].x, bx[k].y, bx[k].z, bx[k].w);
                    float den = __fsub_rn(__fadd_rn(ra, ark), inter);
                    if (__fdiv_rn(inter, den) > NMS_THR)
                        atomicOr(&s_keep[j >> 6], 1ull << (j & 63));
                }
            }
        }
        __syncthreads();
        cnt++;
        if (cnt >= MAXN) break;
    }
    for (int r2 = tid; r2 < cnt; r2 += 1024) {
        int rk = s_kept[r2];
        g_kept_slot[c*MAXN + r2]  = g_sorted_slot[c*KPRE + rk];
        g_kept_score[c*MAXN + r2] = g_sorted_score[c*KPRE + rk];
    }
    if (tid == 0) g_kept_cnt[c] = cnt;
}

// ---------------- kernel 8: merge + final top-500 + output ----------------
__global__ void __launch_bounds__(1024) final_merge(float* __restrict__ out) {
    __shared__ unsigned long long sm[2048];
    for (int t = threadIdx.x; t < 2048; t += 1024) {
        unsigned long long key = 0ull;
        if (t < 3*MAXN) {
            int c = t / MAXN, pos = t % MAXN;
            if (pos < g_kept_cnt[c]) {
                float sc = g_kept_score[c*MAXN + pos];
                unsigned flat = (unsigned)(c*KPRE + pos);
                key = ((unsigned long long)__float_as_uint(sc) << 32) | (unsigned)(~flat);
            }
        }
        sm[t] = key;
    }
    __syncthreads();
    for (unsigned k = 2; k <= 2048; k <<= 1) {
        for (unsigned j = k >> 1; j > 0; j >>= 1) {
            for (unsigned t = threadIdx.x; t < 2048; t += 1024) {
                unsigned ixj = t ^ j;
                if (ixj > t) {
                    unsigned long long A = sm[t], B = sm[ixj];
                    if ((A < B) == ((t & k) == 0)) { sm[t] = B; sm[ixj] = A; }
                }
            }
            __syncthreads();
        }
    }
    for (int r = threadIdx.x; r < MAXN; r += 1024) {
        unsigned long long key = sm[r];
        if (key != 0ull) {
            float score = __uint_as_float((unsigned)(key >> 32));
            unsigned flat = ~(unsigned)(key & 0xFFFFFFFFu);
            int c = (int)(flat >> 12);
            int pos = (int)(flat & 4095u);
            int slot = g_kept_slot[c*MAXN + pos];
            float b[7];
#pragma unroll
            for (int k = 0; k < 7; k++) b[k] = g_box[slot*7 + k];
            float rr = b[6];
            float dir_rot = __fsub_rn(__fadd_rn(rr, PIH_F),
                                      __fmul_rn(floorf(__fadd_rn(rr, 0.5f)), PI_F));
            b[6] = __fadd_rn(__fsub_rn(dir_rot, PIH_F), __fmul_rn(PI_F, g_dirf[slot]));
#pragma unroll
            for (int k = 0; k < 7; k++) out[r*7 + k] = b[k];
            out[7*MAXN + r] = score;
            out[8*MAXN + r] = (float)c;
        } else {
#pragma unroll
            for (int k = 0; k < 7; k++) out[r*7 + k] = 0.f;
            out[7*MAXN + r] = 0.f;
            out[8*MAXN + r] = -1.f;
        }
    }
}

// ---------------- launch ----------------
extern "C" void kernel_launch(void* const* d_in, const int* in_sizes, int n_in,
                              void* d_out, int out_size) {
    const float* cls    = (const float*)d_in[0];
    const float* bp     = (const float*)d_in[1];
    const float* dirp   = (const float*)d_in[2];
    const float* priors = (const float*)d_in[3];
    float* out = (float*)d_out;

    cudaFuncSetAttribute(nms_reduce, cudaFuncAttributeMaxDynamicSharedMemorySize, DSM_TOTAL);

    zero_kernel<<<256, 256>>>();
    score_hist<<<(HW/4 + 255) / 256, 256>>>(cls);
    find_thr1<<<1, 1024>>>();
    compact1<<<(NANCH/4 + 255) / 256, 256>>>();
    level2<<<1, 1024>>>();
    sort_topk<<<1, 1024>>>();
    decode_kernel<<<(KPRE + 255) / 256, 256>>>(cls, bp, dirp, priors);
    sort_class<<<3, 1024>>>();
    nms_reduce<<<3, 1024, DSM_TOTAL>>>();
    final_merge<<<1, 1024>>>(out);
}

// round 10
// speedup vs baseline: 1.6352x; 1.0275x over previous
#include <cuda_runtime.h>
#include <cuda_fp16.h>
#include <math.h>

#define HH 496
#define WW 432
#define HW (HH*WW)            // 214272
#define APL 6
#define NANCH (HW*APL)        // 1285632
#define KPRE 4096
#define MAXN 500
#define SCORE_THR 0.1f
#define NMS_THR 0.5f
#define CAND_CAP (1<<18)
#define TIE_CAP 4096
#define PI_F 3.14159265358979323846f
#define PIH_F 1.57079632679489661923f

// NMS spatial-grid constants
#define CSX 35
#define CSY 40
#define NCELL (CSX*CSY)       // 1400
#define EDGE_CAP 16384
#define DEG_CAP 64

// dynamic smem layout (bytes)
#define OFF_PC        0                      // uint2[4096]        32768
#define OFF_CLIST     32768                  // u16[4096]           8192
#define OFF_OFFS      40960                  // u16[4100]           8200 (pad)
#define OFF_EDGES     49168                  // u16[EDGE_CAP]      32768
#define OFF_CCNT      81936                  // int[NCELL]          5600
#define OFF_CSTART    87536                  // int[NCELL+1]        5604 (pad)
#define OFF_KEEP      93152                  // u64[64]              512
#define OFF_KEPT      93664                  // int[MAXN]           2000
#define OFF_MISC      95664                  // int[96]              384
#define OFF_ELIST     96048                  // u16[4096]           8192
#define DSM_TOTAL     104448

// ---------------- device scratch (static, no allocations) ----------------
__device__ unsigned g_key[NANCH];            // layout [a][HW]
__device__ unsigned g_hist[65536];
__device__ unsigned g_hist2[65536];
__device__ int g_cntHi;
__device__ int g_candCnt;
__device__ int g_tieCnt;
__device__ int g_thr1;
__device__ int g_k2;
__device__ unsigned g_cand_key[CAND_CAP];
__device__ int      g_cand_idx[CAND_CAP];
__device__ int      g_tie[TIE_CAP];
__device__ int      g_topk_idx[KPRE];        // original flat index s*APL+a
__device__ unsigned g_topk_key[KPRE];
__device__ float    g_sc[KPRE*3];
__device__ float    g_dirf[KPRE];
__device__ float    g_box[KPRE*7];
__device__ float4   g_xyxy[KPRE];
__device__ int      g_sorted_slot[3*KPRE];
__device__ float    g_sorted_score[3*KPRE];
__device__ float4   g_sxy[3*KPRE];
__device__ int      g_kept_slot[3*MAXN];
__device__ float    g_kept_score[3*MAXN];
__device__ int      g_kept_cnt[3];

__device__ __forceinline__ float sigd(float x) {
    // double-rounded sigmoid: matches fp32 reference sigmoid to <=1ulp
    return (float)(1.0 / (1.0 + exp(-(double)x)));
}

__device__ __forceinline__ unsigned mono_key(float m) {
    // order-preserving map fp32 -> u32 (sigmoid is monotone in the logit)
    unsigned b = __float_as_uint(m);
    return (b & 0x80000000u) ? ~b : (b | 0x80000000u);
}

__device__ __forceinline__ float area_rn(float x1, float y1, float x2, float y2) {
    return __fmul_rn(__fadd_rn(__fsub_rn(x2, x1), 1.f),
                     __fadd_rn(__fsub_rn(y2, y1), 1.f));
}

__device__ __forceinline__ void agg_hist_add(unsigned bin) {
    // warp-aggregated histogram increment (keys cluster -> few atomics)
    unsigned act = __activemask();
    unsigned mask = __match_any_sync(act, bin);
    int leader = __ffs(mask) - 1;
    if ((int)(threadIdx.x & 31) == leader)
        atomicAdd(&g_hist[bin], (unsigned)__popc(mask));
}

// ---------------- kernel 0: zero scratch ----------------
__global__ void zero_kernel() {
    int t = blockIdx.x * blockDim.x + threadIdx.x;
    if (t < 65536) { g_hist[t] = 0u; g_hist2[t] = 0u; }
    if (t == 0) { g_cntHi = 0; g_candCnt = 0; g_tieCnt = 0; }
}

// ---------------- kernel 1: per-anchor max-logit key + histogram (vectorized) ----------------
__global__ void score_hist(const float* __restrict__ cls) {
    int t = blockIdx.x * blockDim.x + threadIdx.x;
    if (t >= HW/4) return;
    int s = t * 4;
#pragma unroll
    for (int a = 0; a < APL; a++) {
        const float4 v0 = *reinterpret_cast<const float4*>(cls + (size_t)(a*3+0)*HW + s);
        const float4 v1 = *reinterpret_cast<const float4*>(cls + (size_t)(a*3+1)*HW + s);
        const float4 v2 = *reinterpret_cast<const float4*>(cls + (size_t)(a*3+2)*HW + s);
        unsigned k0 = mono_key(fmaxf(fmaxf(v0.x, v1.x), v2.x));
        unsigned k1 = mono_key(fmaxf(fmaxf(v0.y, v1.y), v2.y));
        unsigned k2 = mono_key(fmaxf(fmaxf(v0.z, v1.z), v2.z));
        unsigned k3 = mono_key(fmaxf(fmaxf(v0.w, v1.w), v2.w));
        *reinterpret_cast<uint4*>(g_key + (size_t)a*HW + s) = make_uint4(k0, k1, k2, k3);
        agg_hist_add(k0 >> 16);
        agg_hist_add(k1 >> 16);
        agg_hist_add(k2 >> 16);
        agg_hist_add(k3 >> 16);
    }
}

// ---------------- kernel 2: find level-1 threshold bin (coalesced chunk sums) ----------------
__global__ void __launch_bounds__(1024) find_thr1() {
    __shared__ unsigned csum[1024];
    int wid = threadIdx.x >> 5, lane = threadIdx.x & 31;
    for (int cc = wid; cc < 1024; cc += 32) {
        unsigned v = g_hist[cc*64 + lane] + g_hist[cc*64 + 32 + lane];
#pragma unroll
        for (int o = 16; o > 0; o >>= 1) v += __shfl_down_sync(0xFFFFFFFFu, v, o);
        if (lane == 0) csum[cc] = v;
    }
    __syncthreads();
    if (threadIdx.x == 0) {
        unsigned acc = 0; int ch;
        for (ch = 1023; ch >= 0; ch--) {
            if (acc + csum[ch] >= (unsigned)KPRE) break;
            acc += csum[ch];
        }
        unsigned C1 = acc; int T = ch * 64;
        for (int b = 63; b >= 0; b--) {
            unsigned h = g_hist[ch*64 + b];
            if (C1 + h >= (unsigned)KPRE) { T = ch*64 + b; break; }
            C1 += h;
        }
        g_thr1 = T;
        g_k2 = KPRE - (int)C1;
    }
}

// ---------------- kernel 3: compact winners + boundary candidates (vectorized) ----------------
__global__ void compact1() {
    int p = blockIdx.x * blockDim.x + threadIdx.x;
    if (p >= NANCH/4) return;
    uint4 kv = *reinterpret_cast<const uint4*>(g_key + 4*(size_t)p);
    unsigned ks[4] = {kv.x, kv.y, kv.z, kv.w};
    int T = g_thr1;
#pragma unroll
    for (int j = 0; j < 4; j++) {
        unsigned key = ks[j];
        int bin = (int)(key >> 16);
        if (bin >= T) {
            int pos = 4*p + j;             // position in [a][HW] layout
            int a = pos / HW, s = pos - a*HW;
            int iorig = s*APL + a;
            if (bin > T) {
                int q = atomicAdd(&g_cntHi, 1);
                g_topk_idx[q] = iorig; g_topk_key[q] = key;
            } else {
                int q = atomicAdd(&g_candCnt, 1);
                if (q < CAND_CAP) { g_cand_key[q] = key; g_cand_idx[q] = iorig; }
            }
        }
    }
}

// ---------------- kernel 4: level-2 refinement + exact tie-break ----------------
__global__ void __launch_bounds__(1024) level2() {
    __shared__ unsigned csum[1024];
    __shared__ int sT2, sk3;
    int wid = threadIdx.x >> 5, lane = threadIdx.x & 31;
    int nc = min(g_candCnt, CAND_CAP);
    int k2 = g_k2;
    for (int t = threadIdx.x; t < nc; t += 1024)
        atomicAdd(&g_hist2[g_cand_key[t] & 0xFFFFu], 1u);
    __syncthreads();
    for (int cc = wid; cc < 1024; cc += 32) {
        unsigned v = g_hist2[cc*64 + lane] + g_hist2[cc*64 + 32 + lane];
#pragma unroll
        for (int o = 16; o > 0; o >>= 1) v += __shfl_down_sync(0xFFFFFFFFu, v, o);
        if (lane == 0) csum[cc] = v;
    }
    __syncthreads();
    if (threadIdx.x == 0) {
        unsigned acc = 0; int ch;
        for (ch = 1023; ch >= 0; ch--) {
            if (acc + csum[ch] >= (unsigned)k2) break;
            acc += csum[ch];
        }
        unsigned C1 = acc; int T = ch * 64;
        for (int b = 63; b >= 0; b--) {
            unsigned h = g_hist2[ch*64 + b];
            if (C1 + h >= (unsigned)k2) { T = ch*64 + b; break; }
            C1 += h;
        }
        sT2 = T; sk3 = k2 - (int)C1;
    }
    __syncthreads();
    int T2 = sT2;
    for (int t = threadIdx.x; t < nc; t += 1024) {
        int low = (int)(g_cand_key[t] & 0xFFFFu);
        if (low > T2) {
            int p = atomicAdd(&g_cntHi, 1);
            g_topk_idx[p] = g_cand_idx[t];
            g_topk_key[p] = g_cand_key[t];
        } else if (low == T2) {
            int p = atomicAdd(&g_tieCnt, 1);
            if (p < TIE_CAP) g_tie[p] = g_cand_idx[t];
        }
    }
    __syncthreads();
    int m = min(g_tieCnt, TIE_CAP);
    int k3 = sk3;
    unsigned tie_key = ((unsigned)g_thr1 << 16) | (unsigned)T2;
    for (int t = threadIdx.x; t < m; t += 1024) {
        int idx = g_tie[t];
        int rank = 0;
        for (int u = 0; u < m; u++) rank += (g_tie[u] < idx) ? 1 : 0;
        if (rank < k3) {
            int p = atomicAdd(&g_cntHi, 1);
            g_topk_idx[p] = idx; g_topk_key[p] = tie_key;
        }
    }
}

// ---------------- kernel 4b: canonicalize top-k order (key desc, idx asc) ----------------
__global__ void __launch_bounds__(1024) sort_topk() {
    __shared__ unsigned long long sm[KPRE];
    for (int t = threadIdx.x; t < KPRE; t += 1024) {
        sm[t] = ((unsigned long long)g_topk_key[t] << 32) | (unsigned)(~(unsigned)g_topk_idx[t]);
    }
    __syncthreads();
    for (unsigned k = 2; k <= KPRE; k <<= 1) {
        for (unsigned j = k >> 1; j > 0; j >>= 1) {
            for (unsigned t = threadIdx.x; t < KPRE; t += 1024) {
                unsigned ixj = t ^ j;
                if (ixj > t) {
                    unsigned long long A = sm[t], B = sm[ixj];
                    if ((A < B) == ((t & k) == 0)) { sm[t] = B; sm[ixj] = A; }  // descending
                }
            }
            __syncthreads();
        }
    }
    for (int t = threadIdx.x; t < KPRE; t += 1024)
        g_topk_idx[t] = (int)(~(unsigned)(sm[t] & 0xFFFFFFFFu));
}

// ---------------- kernel 5: gather + decode the 4096 selected anchors ----------------
__global__ void decode_kernel(const float* __restrict__ cls, const float* __restrict__ bp,
                              const float* __restrict__ dirp, const float* __restrict__ priors) {
    int t = blockIdx.x * blockDim.x + threadIdx.x;
    if (t >= KPRE) return;
    int i = g_topk_idx[t];
    int s = i / APL, a = i - s * APL;
#pragma unroll
    for (int c = 0; c < 3; c++)
        g_sc[t*3 + c] = sigd(cls[(a*3 + c)*HW + s]);
    float dv0 = dirp[(a*2 + 0)*HW + s];
    float dv1 = dirp[(a*2 + 1)*HW + s];
    g_dirf[t] = (dv1 > dv0) ? 1.f : 0.f;

    float dl[7], an[7];
#pragma unroll
    for (int k = 0; k < 7; k++) {
        dl[k] = bp[(a*7 + k)*HW + s];
        an[k] = priors[(size_t)i*7 + k];
    }
    float za   = __fadd_rn(an[2], __fmul_rn(an[5], 0.5f));
    float diag = sqrtf(__fadd_rn(__fmul_rn(an[4], an[4]), __fmul_rn(an[3], an[3])));
    float xg = __fadd_rn(__fmul_rn(dl[0], diag), an[0]);
    float yg = __fadd_rn(__fmul_rn(dl[1], diag), an[1]);
    float zg = __fadd_rn(__fmul_rn(dl[2], an[5]), za);
    float wg = __fmul_rn(expf(dl[3]), an[3]);
    float lg = __fmul_rn(expf(dl[4]), an[4]);
    float hg = __fmul_rn(expf(dl[5]), an[5]);
    float rg = __fadd_rn(dl[6], an[6]);
    zg = __fsub_rn(zg, __fmul_rn(hg, 0.5f));
    g_box[t*7+0]=xg; g_box[t*7+1]=yg; g_box[t*7+2]=zg;
    g_box[t*7+3]=wg; g_box[t*7+4]=lg; g_box[t*7+5]=hg; g_box[t*7+6]=rg;
    g_xyxy[t] = make_float4(__fsub_rn(xg, __fmul_rn(wg, 0.5f)),
                            __fsub_rn(yg, __fmul_rn(lg, 0.5f)),
                            __fadd_rn(xg, __fmul_rn(wg, 0.5f)),
                            __fadd_rn(yg, __fmul_rn(lg, 0.5f)));
}

// ---------------- kernel 6: per-class bitonic sort (score desc, topk-pos asc) ----------------
__global__ void __launch_bounds__(1024) sort_class() {
    int c = blockIdx.x;
    __shared__ unsigned long long sm[KPRE];
    for (int t = threadIdx.x; t < KPRE; t += 1024) {
        float sc = g_sc[t*3 + c];
        sm[t] = ((unsigned long long)__float_as_uint(sc) << 32) | (unsigned)(~(unsigned)t);
    }
    __syncthreads();
    for (unsigned k = 2; k <= KPRE; k <<= 1) {
        for (unsigned j = k >> 1; j > 0; j >>= 1) {
            for (unsigned t = threadIdx.x; t < KPRE; t += 1024) {
                unsigned ixj = t ^ j;
                if (ixj > t) {
                    unsigned long long A = sm[t], B = sm[ixj];
                    if ((A < B) == ((t & k) == 0)) { sm[t] = B; sm[ixj] = A; }
                }
            }
            __syncthreads();
        }
    }
    for (int t = threadIdx.x; t < KPRE; t += 1024) {
        unsigned long long key = sm[t];
        int slot = (int)(~(unsigned)(key & 0xFFFFFFFFu));
        g_sorted_slot[c*KPRE + t] = slot;
        g_sorted_score[c*KPRE + t] = __uint_as_float((unsigned)(key >> 32));
        g_sxy[c*KPRE + t] = g_xyxy[slot];
    }
}

// ---------------- kernel 7: NMS via sparse suppression edges ----------------
__global__ void __launch_bounds__(1024) nms_reduce() {
    extern __shared__ char dsm[];
    uint2*              s_pc     = (uint2*)(dsm + OFF_PC);
    unsigned short*     s_clist  = (unsigned short*)(dsm + OFF_CLIST);
    unsigned short*     s_offs   = (unsigned short*)(dsm + OFF_OFFS);
    unsigned short*     s_edges  = (unsigned short*)(dsm + OFF_EDGES);
    int*                s_ccnt   = (int*)(dsm + OFF_CCNT);
    int*                s_cstart = (int*)(dsm + OFF_CSTART);
    unsigned long long* s_keep   = (unsigned long long*)(dsm + OFF_KEEP);
    int*                s_kept   = (int*)(dsm + OFF_KEPT);
    int*                s_misc   = (int*)(dsm + OFF_MISC);
    float*              s_miscf  = (float*)(dsm + OFF_MISC);
    unsigned short*     s_elist  = (unsigned short*)(dsm + OFF_ELIST);

    int c = blockIdx.x, tid = threadIdx.x;
    int lane = tid & 31, wid = tid >> 5;
    const unsigned FULL = 0xFFFFFFFFu;

    // --- load 4 contiguous-by-rank boxes; publish packed half data; bin ---
    float4 bx[4]; float cxr[4], cyr[4], hxr[4], hyr[4];
    int cel[4], pos[4];
    float mhx = 0.f, mhy = 0.f;
#pragma unroll
    for (int k = 0; k < 4; k++) {
        int r = 4*tid + k;
        float4 b = g_sxy[c*KPRE + r];
        bx[k] = b;
        cxr[k] = (b.x + b.z) * 0.5f;  cyr[k] = (b.y + b.w) * 0.5f;
        hxr[k] = (b.z - b.x) * 0.5f;  hyr[k] = (b.w - b.y) * 0.5f;
        mhx = fmaxf(mhx, hxr[k]);     mhy = fmaxf(mhy, hyr[k]);
        int ix = min(CSX-1, max(0, (int)(cxr[k]*0.5f)));
        int iy = min(CSY-1, max(0, (int)((cyr[k]+40.f)*0.5f)));
        cel[k] = iy*CSX + ix;
        __half2 pcc = __floats2half2_rn(cxr[k], cyr[k]);
        __half2 phh = __floats2half2_rn(hxr[k], hyr[k]);
        uint2 u;
        u.x = *reinterpret_cast<unsigned*>(&pcc);
        u.y = *reinterpret_cast<unsigned*>(&phh);
        s_pc[r] = u;
    }
    for (int t = tid; t < NCELL; t += 1024) s_ccnt[t] = 0;
    if (tid == 0) s_misc[73] = 0;    // overflow flag
#pragma unroll
    for (int o = 16; o > 0; o >>= 1) {
        mhx = fmaxf(mhx, __shfl_xor_sync(FULL, mhx, o));
        mhy = fmaxf(mhy, __shfl_xor_sync(FULL, mhy, o));
    }
    __syncthreads();
    if (lane == 0) { s_miscf[wid] = mhx; s_miscf[40 + wid] = mhy; }
    __syncthreads();
    if (tid == 0) {
        float a = 0.f, b2 = 0.f;
        for (int w = 0; w < 32; w++) { a = fmaxf(a, s_miscf[w]); b2 = fmaxf(b2, s_miscf[40+w]); }
        s_miscf[84] = a; s_miscf[85] = b2;
    }
#pragma unroll
    for (int k = 0; k < 4; k++) pos[k] = atomicAdd(&s_ccnt[cel[k]], 1);
    __syncthreads();

    // --- exclusive scan cell counts -> cell starts (2 cells per thread) ---
    int i0 = tid*2, i1 = tid*2 + 1;
    int v0 = (i0 < NCELL) ? s_ccnt[i0] : 0;
    int v1 = (i1 < NCELL) ? s_ccnt[i1] : 0;
    int ts = v0 + v1, xs = ts;
#pragma unroll
    for (int o = 1; o < 32; o <<= 1) { int y = __shfl_up_sync(FULL, xs, o); if (lane >= o) xs += y; }
    if (lane == 31) s_misc[wid] = xs;
    __syncthreads();
    if (wid == 0) {
        int w = s_misc[lane];
#pragma unroll
        for (int o = 1; o < 32; o <<= 1) { int y = __shfl_up_sync(FULL, w, o); if (lane >= o) w += y; }
        s_misc[lane] = w;
    }
    __syncthreads();
    int cbase = (wid ? s_misc[wid-1] : 0) + (xs - ts);
    if (i0 < NCELL) s_cstart[i0] = cbase;
    if (i1 < NCELL) s_cstart[i1] = cbase + v0;
    if (tid == 1023) s_cstart[NCELL] = cbase + ts;
    __syncthreads();
#pragma unroll
    for (int k = 0; k < 4; k++)
        s_clist[s_cstart[cel[k]] + pos[k]] = (unsigned short)(4*tid + k);
    __syncthreads();

    // --- edge scan: suppressors i<r with exact IoU > thr ---
    float MHX = s_miscf[84], MHY = s_miscf[85];
    int nrx = min(CSX-1, (int)((2.f*MHX + 1.6f)*0.5f) + 1);
    int nry = min(CSY-1, (int)((2.f*MHY + 1.6f)*0.5f) + 1);

    unsigned short lbuf[4][DEG_CAP];
    int deg[4];
    bool over = false;
#pragma unroll
    for (int k = 0; k < 4; k++) {
        deg[k] = 0;
        int r = 4*tid + k;
        int ixc = cel[k] % CSX, iyc = cel[k] / CSX;
        float mycx = cxr[k], mycy = cyr[k], myhx = hxr[k], myhy = hyr[k];
        float aj = area_rn(bx[k].x, bx[k].y, bx[k].z, bx[k].w);
        int y0 = max(0, iyc-nry), y1 = min(CSY-1, iyc+nry);
        int x0 = max(0, ixc-nrx), x1 = min(CSX-1, ixc+nrx);
        for (int iy = y0; iy <= y1; iy++) {
            int rowb = iy*CSX;
            int qs = s_cstart[rowb + x0];
            int qe = s_cstart[rowb + x1 + 1];
            for (int q = qs; q < qe; q++) {
                int i = s_clist[q];
                if (i >= r) continue;
                uint2 u = s_pc[i];
                __half2 hcc = *reinterpret_cast<__half2*>(&u.x);
                __half2 hhh = *reinterpret_cast<__half2*>(&u.y);
                float2 cc = __half22float2(hcc);
                float2 hh = __half22float2(hhh);
                if (fabsf(cc.x - mycx) < hh.x + myhx + 1.3f &&
                    fabsf(cc.y - mycy) < hh.y + myhy + 1.3f) {
                    float4 ob = __ldg(&g_sxy[c*KPRE + i]);
                    float xx1 = fmaxf(ob.x, bx[k].x), yy1 = fmaxf(ob.y, bx[k].y);
                    float xx2 = fminf(ob.z, bx[k].z), yy2 = fminf(ob.w, bx[k].w);
                    float w  = __fadd_rn(__fsub_rn(xx2, xx1), 1.f);
                    float h2 = __fadd_rn(__fsub_rn(yy2, yy1), 1.f);
                    if (w > 0.f && h2 > 0.f) {
                        float inter = __fmul_rn(w, h2);
                        float ai = area_rn(ob.x, ob.y, ob.z, ob.w);
                        float den = __fsub_rn(__fadd_rn(ai, aj), inter);
                        if (__fdiv_rn(inter, den) > NMS_THR) {
                            if (deg[k] < DEG_CAP) lbuf[k][deg[k]] = (unsigned short)i;
                            deg[k]++;
                        }
                    }
                }
            }
        }
        if (deg[k] > DEG_CAP) over = true;
    }

    // --- packed CSR scan: low20 = edge counts (deg saturated), high = edged-box count ---
    int sdeg[4], ecnt = 0, tsum = 0;
#pragma unroll
    for (int k = 0; k < 4; k++) {
        sdeg[k] = min(deg[k], DEG_CAP + 1);
        tsum += sdeg[k];
        if (deg[k] > 0) ecnt++;
    }
    int val = tsum | (ecnt << 20);
    int xe = val;
#pragma unroll
    for (int o = 1; o < 32; o <<= 1) { int y = __shfl_up_sync(FULL, xe, o); if (lane >= o) xe += y; }
    if (lane == 31) s_misc[wid] = xe;
    if (over) s_misc[73] = 1;
    __syncthreads();
    if (wid == 0) {
        int w = s_misc[lane];
#pragma unroll
        for (int o = 1; o < 32; o <<= 1) { int y = __shfl_up_sync(FULL, w, o); if (lane >= o) w += y; }
        s_misc[lane] = w;
        if (lane == 31 && (w & 0xFFFFF) > EDGE_CAP) s_misc[73] = 1;
    }
    __syncthreads();
    bool flag = (s_misc[73] != 0);
    if (!flag) {
        int xex = (wid ? s_misc[wid-1] : 0) + (xe - val);   // exclusive packed offset
        int eoff = xex & 0xFFFFF;
        int loff = xex >> 20;
#pragma unroll
        for (int k = 0; k < 4; k++) {
            s_offs[4*tid + k] = (unsigned short)eoff;
            for (int e = 0; e < deg[k]; e++) s_edges[eoff + e] = lbuf[k][e];
            eoff += deg[k];
            if (deg[k] > 0) s_elist[loff++] = (unsigned short)(4*tid + k);
        }
        if (tid == 1023) s_offs[KPRE] = (unsigned short)eoff;
    }
    // valid bits by rank
    if (tid < 64) {
        unsigned long long wv = 0ull;
        for (int b = 0; b < 64; b++)
            if (g_sorted_score[c*KPRE + tid*64 + b] > SCORE_THR) wv |= 1ull << b;
        s_keep[tid] = wv;
    }
    __syncthreads();

    if (!flag) {
        // --- serial resolve over EDGED boxes only (rank-ascending) ---
        if (tid == 0) {
            int ne = s_misc[31] >> 20;
            for (int e2 = 0; e2 < ne; e2++) {
                int j = s_elist[e2];
                unsigned long long bitj = 1ull << (j & 63);
                if (!(s_keep[j >> 6] & bitj)) continue;     // invalid or already gone
                int o = s_offs[j];
                int d = (int)s_offs[j+1] - o;
                bool dead = false;
                for (int e = 0; e < d; e++) {
                    int i = s_edges[o + e];
                    if ((s_keep[i >> 6] >> (i & 63)) & 1ull) { dead = true; break; }
                }
                if (dead) s_keep[j >> 6] &= ~bitj;
            }
        }
        __syncthreads();
        // --- parallel kept-list extraction (rank order) ---
        if (tid < 64) s_misc[tid] = __popcll(s_keep[tid]);
        __syncthreads();
        if (tid == 0) {
            int acc = 0;
            for (int w2 = 0; w2 < 64; w2++) { int v2 = s_misc[w2]; s_misc[w2] = acc; acc += v2; }
            s_misc[80] = acc;
        }
        __syncthreads();
        int total = s_misc[80];
        int kc = min(total, MAXN);
        if (tid < 64) {
            unsigned long long w2 = s_keep[tid];
            int p2 = s_misc[tid];
            while (w2) {
                int b = __ffsll((long long)w2) - 1; w2 &= w2 - 1;
                if (p2 < MAXN) s_kept[p2] = tid*64 + b;
                p2++;
            }
        }
        __syncthreads();
        for (int r2 = tid; r2 < kc; r2 += 1024) {
            int rk = s_kept[r2];
            g_kept_slot[c*MAXN + r2]  = g_sorted_slot[c*KPRE + rk];
            g_kept_score[c*MAXN + r2] = g_sorted_score[c*KPRE + rk];
        }
        if (tid == 0) g_kept_cnt[c] = kc;
        return;
    }

    // --- FALLBACK: iterative greedy loop (rare; guaranteed-correct) ---
    if (tid < 64) s_keep[tid] = ~s_keep[tid];      // now = removed bits
    __syncthreads();
    float* s_ref = &s_miscf[76];
    int cnt = 0, wd0 = 0;
    while (true) {
        if (tid == 0) {
            int found = -1;
            for (int wd = wd0; wd < 64; wd++) {
                unsigned long long avail = ~s_keep[wd];
                if (avail) { found = wd*64 + __ffsll((long long)avail) - 1; wd0 = wd; break; }
            }
            s_misc[75] = found;
            if (found >= 0) {
                s_keep[found >> 6] |= 1ull << (found & 63);
                s_kept[cnt] = found;
            }
        }
        __syncthreads();
        int i = s_misc[75];
        if (i < 0) break;
        if (tid == (i >> 2)) {
            int k = i & 3;
            s_ref[0] = bx[k].x; s_ref[1] = bx[k].y; s_ref[2] = bx[k].z; s_ref[3] = bx[k].w;
        }
        __syncthreads();
        float rx1 = s_ref[0], ry1 = s_ref[1], rx2 = s_ref[2], ry2 = s_ref[3];
        float ra = area_rn(rx1, ry1, rx2, ry2);
#pragma unroll
        for (int k = 0; k < 4; k++) {
            int j = 4*tid + k;
            if (j > i && !((s_keep[j >> 6] >> (j & 63)) & 1ull)) {
                float xx1 = fmaxf(rx1, bx[k].x), yy1 = fmaxf(ry1, bx[k].y);
                float xx2 = fminf(rx2, bx[k].z), yy2 = fminf(ry2, bx[k].w);
                float w  = __fadd_rn(__fsub_rn(xx2, xx1), 1.f);
                float h2 = __fadd_rn(__fsub_rn(yy2, yy1), 1.f);
                if (w > 0.f && h2 > 0.f) {
                    float inter = __fmul_rn(w, h2);
                    float ark = area_rn(bx[k].x, bx[k].y, bx[k].z, bx[k].w);
                    float den = __fsub_rn(__fadd_rn(ra, ark), inter);
                    if (__fdiv_rn(inter, den) > NMS_THR)
                        atomicOr(&s_keep[j >> 6], 1ull << (j & 63));
                }
            }
        }
        __syncthreads();
        cnt++;
        if (cnt >= MAXN) break;
    }
    for (int r2 = tid; r2 < cnt; r2 += 1024) {
        int rk = s_kept[r2];
        g_kept_slot[c*MAXN + r2]  = g_sorted_slot[c*KPRE + rk];
        g_kept_score[c*MAXN + r2] = g_sorted_score[c*KPRE + rk];
    }
    if (tid == 0) g_kept_cnt[c] = cnt;
}

// ---------------- kernel 8: merge + final top-500 + output ----------------
__global__ void __launch_bounds__(1024) final_merge(float* __restrict__ out) {
    __shared__ unsigned long long sm[2048];
    for (int t = threadIdx.x; t < 2048; t += 1024) {
        unsigned long long key = 0ull;
        if (t < 3*MAXN) {
            int c = t / MAXN, pos = t % MAXN;
            if (pos < g_kept_cnt[c]) {
                float sc = g_kept_score[c*MAXN + pos];
                unsigned flat = (unsigned)(c*KPRE + pos);
                key = ((unsigned long long)__float_as_uint(sc) << 32) | (unsigned)(~flat);
            }
        }
        sm[t] = key;
    }
    __syncthreads();
    for (unsigned k = 2; k <= 2048; k <<= 1) {
        for (unsigned j = k >> 1; j > 0; j >>= 1) {
            for (unsigned t = threadIdx.x; t < 2048; t += 1024) {
                unsigned ixj = t ^ j;
                if (ixj > t) {
                    unsigned long long A = sm[t], B = sm[ixj];
                    if ((A < B) == ((t & k) == 0)) { sm[t] = B; sm[ixj] = A; }
                }
            }
            __syncthreads();
        }
    }
    for (int r = threadIdx.x; r < MAXN; r += 1024) {
        unsigned long long key = sm[r];
        if (key != 0ull) {
            float score = __uint_as_float((unsigned)(key >> 32));
            unsigned flat = ~(unsigned)(key & 0xFFFFFFFFu);
            int c = (int)(flat >> 12);
            int pos = (int)(flat & 4095u);
            int slot = g_kept_slot[c*MAXN + pos];
            float b[7];
#pragma unroll
            for (int k = 0; k < 7; k++) b[k] = g_box[slot*7 + k];
            float rr = b[6];
            float dir_rot = __fsub_rn(__fadd_rn(rr, PIH_F),
                                      __fmul_rn(floorf(__fadd_rn(rr, 0.5f)), PI_F));
            b[6] = __fadd_rn(__fsub_rn(dir_rot, PIH_F), __fmul_rn(PI_F, g_dirf[slot]));
#pragma unroll
            for (int k = 0; k < 7; k++) out[r*7 + k] = b[k];
            out[7*MAXN + r] = score;
            out[8*MAXN + r] = (float)c;
        } else {
#pragma unroll
            for (int k = 0; k < 7; k++) out[r*7 + k] = 0.f;
            out[7*MAXN + r] = 0.f;
            out[8*MAXN + r] = -1.f;
        }
    }
}

// ---------------- launch ----------------
extern "C" void kernel_launch(void* const* d_in, const int* in_sizes, int n_in,
                              void* d_out, int out_size) {
    const float* cls    = (const float*)d_in[0];
    const float* bp     = (const float*)d_in[1];
    const float* dirp   = (const float*)d_in[2];
    const float* priors = (const float*)d_in[3];
    float* out = (float*)d_out;

    cudaFuncSetAttribute(nms_reduce, cudaFuncAttributeMaxDynamicSharedMemorySize, DSM_TOTAL);

    zero_kernel<<<256, 256>>>();
    score_hist<<<(HW/4 + 255) / 256, 256>>>(cls);
    find_thr1<<<1, 1024>>>();
    compact1<<<(NANCH/4 + 255) / 256, 256>>>();
    level2<<<1, 1024>>>();
    sort_topk<<<1, 1024>>>();
    decode_kernel<<<(KPRE + 255) / 256, 256>>>(cls, bp, dirp, priors);
    sort_class<<<3, 1024>>>();
    nms_reduce<<<3, 1024, DSM_TOTAL>>>();
    final_merge<<<1, 1024>>>(out);
}

// round 11
// speedup vs baseline: 2.0023x; 1.2245x over previous
#include <cuda_runtime.h>
#include <cuda_fp16.h>
#include <math.h>

#define HH 496
#define WW 432
#define HW (HH*WW)            // 214272
#define APL 6
#define NANCH (HW*APL)        // 1285632
#define KPRE 4096
#define MAXN 500
#define SCORE_THR 0.1f
#define NMS_THR 0.5f
#define CAND_CAP (1<<18)
#define TIE_CAP 4096
#define PI_F 3.14159265358979323846f
#define PIH_F 1.57079632679489661923f

// NMS spatial-grid constants
#define CSX 35
#define CSY 40
#define NCELL (CSX*CSY)       // 1400
#define EDGE_CAP 16384
#define DEGG 16               // per-box global edge slots

// nms_resolve dynamic smem layout (bytes)
#define ROFF_EDGES 0          // u16[EDGE_CAP]  32768
#define ROFF_OFFS  32768      // u16[4100]       8200
#define ROFF_ELIST 40968      // u16[4096]       8192
#define ROFF_KEEP  49160      // u64[64]          512
#define ROFF_KEPT  49672      // int[MAXN]       2000
#define ROFF_MISC  51672      // int[96]          384
#define RDSM_TOTAL 52096

// ---------------- device scratch (static, no allocations) ----------------
__device__ unsigned g_key[NANCH];            // layout [a][HW]
__device__ unsigned g_hist[65536];
__device__ unsigned g_hist2[65536];
__device__ int g_cntHi;
__device__ int g_candCnt;
__device__ int g_tieCnt;
__device__ int g_thr1;
__device__ int g_k2;
__device__ unsigned g_cand_key[CAND_CAP];
__device__ int      g_cand_idx[CAND_CAP];
__device__ int      g_tie[TIE_CAP];
__device__ int      g_topk_idx[KPRE];        // original flat index s*APL+a
__device__ unsigned g_topk_key[KPRE];
__device__ float    g_sc[KPRE*3];
__device__ float    g_dirf[KPRE];
__device__ float    g_box[KPRE*7];
__device__ float4   g_xyxy[KPRE];
__device__ int      g_sorted_slot[3*KPRE];
__device__ float    g_sorted_score[3*KPRE];
__device__ float4   g_sxy[3*KPRE];
__device__ int      g_kept_slot[3*MAXN];
__device__ float    g_kept_score[3*MAXN];
__device__ int      g_kept_cnt[3];
// NMS globals
__device__ unsigned short g_clist2[3*KPRE];
__device__ int      g_cstart2[3*(NCELL+1)];
__device__ float    g_mh[6];                 // per-class MHX, MHY
__device__ unsigned char  g_deg[3*KPRE];
__device__ unsigned short g_edgebuf[3*KPRE*DEGG];
__device__ int      g_overflow[3];

__device__ __forceinline__ float sigd(float x) {
    // double-rounded sigmoid: matches fp32 reference sigmoid to <=1ulp
    return (float)(1.0 / (1.0 + exp(-(double)x)));
}

__device__ __forceinline__ unsigned mono_key(float m) {
    // order-preserving map fp32 -> u32 (sigmoid is monotone in the logit)
    unsigned b = __float_as_uint(m);
    return (b & 0x80000000u) ? ~b : (b | 0x80000000u);
}

__device__ __forceinline__ float area_rn(float x1, float y1, float x2, float y2) {
    return __fmul_rn(__fadd_rn(__fsub_rn(x2, x1), 1.f),
                     __fadd_rn(__fsub_rn(y2, y1), 1.f));
}

__device__ __forceinline__ void agg_hist_add(unsigned bin) {
    unsigned act = __activemask();
    unsigned mask = __match_any_sync(act, bin);
    int leader = __ffs(mask) - 1;
    if ((int)(threadIdx.x & 31) == leader)
        atomicAdd(&g_hist[bin], (unsigned)__popc(mask));
}

// ---------------- kernel 0: zero scratch ----------------
__global__ void zero_kernel() {
    int t = blockIdx.x * blockDim.x + threadIdx.x;
    if (t < 65536) { g_hist[t] = 0u; g_hist2[t] = 0u; }
    if (t == 0) { g_cntHi = 0; g_candCnt = 0; g_tieCnt = 0; }
    if (t < 3) g_overflow[t] = 0;
}

// ---------------- kernel 1: per-anchor max-logit key + histogram (vectorized) ----------------
__global__ void score_hist(const float* __restrict__ cls) {
    int t = blockIdx.x * blockDim.x + threadIdx.x;
    if (t >= HW/4) return;
    int s = t * 4;
#pragma unroll
    for (int a = 0; a < APL; a++) {
        const float4 v0 = *reinterpret_cast<const float4*>(cls + (size_t)(a*3+0)*HW + s);
        const float4 v1 = *reinterpret_cast<const float4*>(cls + (size_t)(a*3+1)*HW + s);
        const float4 v2 = *reinterpret_cast<const float4*>(cls + (size_t)(a*3+2)*HW + s);
        unsigned k0 = mono_key(fmaxf(fmaxf(v0.x, v1.x), v2.x));
        unsigned k1 = mono_key(fmaxf(fmaxf(v0.y, v1.y), v2.y));
        unsigned k2 = mono_key(fmaxf(fmaxf(v0.z, v1.z), v2.z));
        unsigned k3 = mono_key(fmaxf(fmaxf(v0.w, v1.w), v2.w));
        *reinterpret_cast<uint4*>(g_key + (size_t)a*HW + s) = make_uint4(k0, k1, k2, k3);
        agg_hist_add(k0 >> 16);
        agg_hist_add(k1 >> 16);
        agg_hist_add(k2 >> 16);
        agg_hist_add(k3 >> 16);
    }
}

// ---------------- kernel 2: find level-1 threshold bin (coalesced chunk sums) ----------------
__global__ void __launch_bounds__(1024) find_thr1() {
    __shared__ unsigned csum[1024];
    int wid = threadIdx.x >> 5, lane = threadIdx.x & 31;
    for (int cc = wid; cc < 1024; cc += 32) {
        unsigned v = g_hist[cc*64 + lane] + g_hist[cc*64 + 32 + lane];
#pragma unroll
        for (int o = 16; o > 0; o >>= 1) v += __shfl_down_sync(0xFFFFFFFFu, v, o);
        if (lane == 0) csum[cc] = v;
    }
    __syncthreads();
    if (threadIdx.x == 0) {
        unsigned acc = 0; int ch;
        for (ch = 1023; ch >= 0; ch--) {
            if (acc + csum[ch] >= (unsigned)KPRE) break;
            acc += csum[ch];
        }
        unsigned C1 = acc; int T = ch * 64;
        for (int b = 63; b >= 0; b--) {
            unsigned h = g_hist[ch*64 + b];
            if (C1 + h >= (unsigned)KPRE) { T = ch*64 + b; break; }
            C1 += h;
        }
        g_thr1 = T;
        g_k2 = KPRE - (int)C1;
    }
}

// ---------------- kernel 3: compact winners + boundary candidates (vectorized) ----------------
__global__ void compact1() {
    int p = blockIdx.x * blockDim.x + threadIdx.x;
    if (p >= NANCH/4) return;
    uint4 kv = *reinterpret_cast<const uint4*>(g_key + 4*(size_t)p);
    unsigned ks[4] = {kv.x, kv.y, kv.z, kv.w};
    int T = g_thr1;
#pragma unroll
    for (int j = 0; j < 4; j++) {
        unsigned key = ks[j];
        int bin = (int)(key >> 16);
        if (bin >= T) {
            int pos = 4*p + j;             // position in [a][HW] layout
            int a = pos / HW, s = pos - a*HW;
            int iorig = s*APL + a;
            if (bin > T) {
                int q = atomicAdd(&g_cntHi, 1);
                g_topk_idx[q] = iorig; g_topk_key[q] = key;
            } else {
                int q = atomicAdd(&g_candCnt, 1);
                if (q < CAND_CAP) { g_cand_key[q] = key; g_cand_idx[q] = iorig; }
            }
        }
    }
}

// ---------------- kernel 4: level-2 refinement + exact tie-break ----------------
__global__ void __launch_bounds__(1024) level2() {
    __shared__ unsigned csum[1024];
    __shared__ int sT2, sk3;
    int wid = threadIdx.x >> 5, lane = threadIdx.x & 31;
    int nc = min(g_candCnt, CAND_CAP);
    int k2 = g_k2;
    for (int t = threadIdx.x; t < nc; t += 1024)
        atomicAdd(&g_hist2[g_cand_key[t] & 0xFFFFu], 1u);
    __syncthreads();
    for (int cc = wid; cc < 1024; cc += 32) {
        unsigned v = g_hist2[cc*64 + lane] + g_hist2[cc*64 + 32 + lane];
#pragma unroll
        for (int o = 16; o > 0; o >>= 1) v += __shfl_down_sync(0xFFFFFFFFu, v, o);
        if (lane == 0) csum[cc] = v;
    }
    __syncthreads();
    if (threadIdx.x == 0) {
        unsigned acc = 0; int ch;
        for (ch = 1023; ch >= 0; ch--) {
            if (acc + csum[ch] >= (unsigned)k2) break;
            acc += csum[ch];
        }
        unsigned C1 = acc; int T = ch * 64;
        for (int b = 63; b >= 0; b--) {
            unsigned h = g_hist2[ch*64 + b];
            if (C1 + h >= (unsigned)k2) { T = ch*64 + b; break; }
            C1 += h;
        }
        sT2 = T; sk3 = k2 - (int)C1;
    }
    __syncthreads();
    int T2 = sT2;
    for (int t = threadIdx.x; t < nc; t += 1024) {
        int low = (int)(g_cand_key[t] & 0xFFFFu);
        if (low > T2) {
            int p = atomicAdd(&g_cntHi, 1);
            g_topk_idx[p] = g_cand_idx[t];
            g_topk_key[p] = g_cand_key[t];
        } else if (low == T2) {
            int p = atomicAdd(&g_tieCnt, 1);
            if (p < TIE_CAP) g_tie[p] = g_cand_idx[t];
        }
    }
    __syncthreads();
    int m = min(g_tieCnt, TIE_CAP);
    int k3 = sk3;
    unsigned tie_key = ((unsigned)g_thr1 << 16) | (unsigned)T2;
    for (int t = threadIdx.x; t < m; t += 1024) {
        int idx = g_tie[t];
        int rank = 0;
        for (int u = 0; u < m; u++) rank += (g_tie[u] < idx) ? 1 : 0;
        if (rank < k3) {
            int p = atomicAdd(&g_cntHi, 1);
            g_topk_idx[p] = idx; g_topk_key[p] = tie_key;
        }
    }
}

// ---------------- kernel 4b: canonicalize top-k order (key desc, idx asc) ----------------
__global__ void __launch_bounds__(1024) sort_topk() {
    __shared__ unsigned long long sm[KPRE];
    for (int t = threadIdx.x; t < KPRE; t += 1024) {
        sm[t] = ((unsigned long long)g_topk_key[t] << 32) | (unsigned)(~(unsigned)g_topk_idx[t]);
    }
    __syncthreads();
    for (unsigned k = 2; k <= KPRE; k <<= 1) {
        for (unsigned j = k >> 1; j > 0; j >>= 1) {
            for (unsigned t = threadIdx.x; t < KPRE; t += 1024) {
                unsigned ixj = t ^ j;
                if (ixj > t) {
                    unsigned long long A = sm[t], B = sm[ixj];
                    if ((A < B) == ((t & k) == 0)) { sm[t] = B; sm[ixj] = A; }  // descending
                }
            }
            __syncthreads();
        }
    }
    for (int t = threadIdx.x; t < KPRE; t += 1024)
        g_topk_idx[t] = (int)(~(unsigned)(sm[t] & 0xFFFFFFFFu));
}

// ---------------- kernel 5: gather + decode the 4096 selected anchors ----------------
__global__ void decode_kernel(const float* __restrict__ cls, const float* __restrict__ bp,
                              const float* __restrict__ dirp, const float* __restrict__ priors) {
    int t = blockIdx.x * blockDim.x + threadIdx.x;
    if (t >= KPRE) return;
    int i = g_topk_idx[t];
    int s = i / APL, a = i - s * APL;
#pragma unroll
    for (int c = 0; c < 3; c++)
        g_sc[t*3 + c] = sigd(cls[(a*3 + c)*HW + s]);
    float dv0 = dirp[(a*2 + 0)*HW + s];
    float dv1 = dirp[(a*2 + 1)*HW + s];
    g_dirf[t] = (dv1 > dv0) ? 1.f : 0.f;

    float dl[7], an[7];
#pragma unroll
    for (int k = 0; k < 7; k++) {
        dl[k] = bp[(a*7 + k)*HW + s];
        an[k] = priors[(size_t)i*7 + k];
    }
    float za   = __fadd_rn(an[2], __fmul_rn(an[5], 0.5f));
    float diag = sqrtf(__fadd_rn(__fmul_rn(an[4], an[4]), __fmul_rn(an[3], an[3])));
    float xg = __fadd_rn(__fmul_rn(dl[0], diag), an[0]);
    float yg = __fadd_rn(__fmul_rn(dl[1], diag), an[1]);
    float zg = __fadd_rn(__fmul_rn(dl[2], an[5]), za);
    float wg = __fmul_rn(expf(dl[3]), an[3]);
    float lg = __fmul_rn(expf(dl[4]), an[4]);
    float hg = __fmul_rn(expf(dl[5]), an[5]);
    float rg = __fadd_rn(dl[6], an[6]);
    zg = __fsub_rn(zg, __fmul_rn(hg, 0.5f));
    g_box[t*7+0]=xg; g_box[t*7+1]=yg; g_box[t*7+2]=zg;
    g_box[t*7+3]=wg; g_box[t*7+4]=lg; g_box[t*7+5]=hg; g_box[t*7+6]=rg;
    g_xyxy[t] = make_float4(__fsub_rn(xg, __fmul_rn(wg, 0.5f)),
                            __fsub_rn(yg, __fmul_rn(lg, 0.5f)),
                            __fadd_rn(xg, __fmul_rn(wg, 0.5f)),
                            __fadd_rn(yg, __fmul_rn(lg, 0.5f)));
}

// ---------------- kernel 6: per-class bitonic sort (score desc, topk-pos asc) ----------------
__global__ void __launch_bounds__(1024) sort_class() {
    int c = blockIdx.x;
    __shared__ unsigned long long sm[KPRE];
    for (int t = threadIdx.x; t < KPRE; t += 1024) {
        float sc = g_sc[t*3 + c];
        sm[t] = ((unsigned long long)__float_as_uint(sc) << 32) | (unsigned)(~(unsigned)t);
    }
    __syncthreads();
    for (unsigned k = 2; k <= KPRE; k <<= 1) {
        for (unsigned j = k >> 1; j > 0; j >>= 1) {
            for (unsigned t = threadIdx.x; t < KPRE; t += 1024) {
                unsigned ixj = t ^ j;
                if (ixj > t) {
                    unsigned long long A = sm[t], B = sm[ixj];
                    if ((A < B) == ((t & k) == 0)) { sm[t] = B; sm[ixj] = A; }
                }
            }
            __syncthreads();
        }
    }
    for (int t = threadIdx.x; t < KPRE; t += 1024) {
        unsigned long long key = sm[t];
        int slot = (int)(~(unsigned)(key & 0xFFFFFFFFu));
        g_sorted_slot[c*KPRE + t] = slot;
        g_sorted_score[c*KPRE + t] = __uint_as_float((unsigned)(key >> 32));
        g_sxy[c*KPRE + t] = g_xyxy[slot];
    }
}

// ---------------- kernel 7a: per-class cell lists + max extents ----------------
__global__ void __launch_bounds__(1024) nms_cells() {
    __shared__ int s_ccnt[NCELL];
    __shared__ int s_cstart[NCELL+1];
    __shared__ int s_misc[64];
    __shared__ float s_mf[80];
    int c = blockIdx.x, tid = threadIdx.x;
    int lane = tid & 31, wid = tid >> 5;
    const unsigned FULL = 0xFFFFFFFFu;

    for (int t = tid; t < NCELL; t += 1024) s_ccnt[t] = 0;
    __syncthreads();

    int cel[4], pos[4];
    float mhx = 0.f, mhy = 0.f;
#pragma unroll
    for (int k = 0; k < 4; k++) {
        int r = 4*tid + k;
        float4 b = g_sxy[c*KPRE + r];
        float cx = (b.x + b.z) * 0.5f, cy = (b.y + b.w) * 0.5f;
        float hx = (b.z - b.x) * 0.5f, hy = (b.w - b.y) * 0.5f;
        mhx = fmaxf(mhx, hx); mhy = fmaxf(mhy, hy);
        int ix = min(CSX-1, max(0, (int)(cx*0.5f)));
        int iy = min(CSY-1, max(0, (int)((cy+40.f)*0.5f)));
        cel[k] = iy*CSX + ix;
        pos[k] = atomicAdd(&s_ccnt[cel[k]], 1);
    }
#pragma unroll
    for (int o = 16; o > 0; o >>= 1) {
        mhx = fmaxf(mhx, __shfl_xor_sync(FULL, mhx, o));
        mhy = fmaxf(mhy, __shfl_xor_sync(FULL, mhy, o));
    }
    if (lane == 0) { s_mf[wid] = mhx; s_mf[40 + wid] = mhy; }
    __syncthreads();
    if (tid == 0) {
        float a = 0.f, b2 = 0.f;
        for (int w = 0; w < 32; w++) { a = fmaxf(a, s_mf[w]); b2 = fmaxf(b2, s_mf[40+w]); }
        g_mh[c*2] = a; g_mh[c*2+1] = b2;
    }

    // exclusive scan cell counts (2 cells per thread)
    int i0 = tid*2, i1 = tid*2 + 1;
    int v0 = (i0 < NCELL) ? s_ccnt[i0] : 0;
    int v1 = (i1 < NCELL) ? s_ccnt[i1] : 0;
    int ts = v0 + v1, xs = ts;
#pragma unroll
    for (int o = 1; o < 32; o <<= 1) { int y = __shfl_up_sync(FULL, xs, o); if (lane >= o) xs += y; }
    if (lane == 31) s_misc[wid] = xs;
    __syncthreads();
    if (wid == 0) {
        int w = s_misc[lane];
#pragma unroll
        for (int o = 1; o < 32; o <<= 1) { int y = __shfl_up_sync(FULL, w, o); if (lane >= o) w += y; }
        s_misc[lane] = w;
    }
    __syncthreads();
    int cbase = (wid ? s_misc[wid-1] : 0) + (xs - ts);
    if (i0 < NCELL) s_cstart[i0] = cbase;
    if (i1 < NCELL) s_cstart[i1] = cbase + v0;
    if (tid == 1023) s_cstart[NCELL] = cbase + ts;
    __syncthreads();
#pragma unroll
    for (int k = 0; k < 4; k++)
        g_clist2[c*KPRE + s_cstart[cel[k]] + pos[k]] = (unsigned short)(4*tid + k);
    for (int t = tid; t <= NCELL; t += 1024)
        g_cstart2[c*(NCELL+1) + t] = s_cstart[t];
}

// ---------------- kernel 7b: edge build — 1 box/thread, 24 blocks, zero local arrays ----------------
__global__ void __launch_bounds__(512) nms_edges() {
    __shared__ uint2 s_pc[KPRE];                 // packed half cx,cy | hx,hy
    __shared__ unsigned short s_clist[KPRE];
    __shared__ int s_cstart[NCELL+1];
    int c = blockIdx.x >> 3, chunk = blockIdx.x & 7, tid = threadIdx.x;

    for (int i = tid; i < KPRE; i += 512) {
        float4 b = g_sxy[c*KPRE + i];
        __half2 pcc = __floats2half2_rn((b.x + b.z)*0.5f, (b.y + b.w)*0.5f);
        __half2 phh = __floats2half2_rn((b.z - b.x)*0.5f, (b.w - b.y)*0.5f);
        uint2 u;
        u.x = *reinterpret_cast<unsigned*>(&pcc);
        u.y = *reinterpret_cast<unsigned*>(&phh);
        s_pc[i] = u;
        s_clist[i] = g_clist2[c*KPRE + i];
    }
    for (int i = tid; i <= NCELL; i += 512)
        s_cstart[i] = g_cstart2[c*(NCELL+1) + i];
    __syncthreads();

    int r = chunk*512 + tid;
    float4 b = g_sxy[c*KPRE + r];
    float mycx = (b.x + b.z)*0.5f, mycy = (b.y + b.w)*0.5f;
    float myhx = (b.z - b.x)*0.5f, myhy = (b.w - b.y)*0.5f;
    float aj = area_rn(b.x, b.y, b.z, b.w);
    float MHX = g_mh[c*2], MHY = g_mh[c*2+1];
    int nrx = min(CSX-1, (int)((2.f*MHX + 1.6f)*0.5f) + 1);
    int nry = min(CSY-1, (int)((2.f*MHY + 1.6f)*0.5f) + 1);
    int ixc = min(CSX-1, max(0, (int)(mycx*0.5f)));
    int iyc = min(CSY-1, max(0, (int)((mycy+40.f)*0.5f)));

    int deg = 0;
    size_t ebase = ((size_t)c*KPRE + r) * DEGG;
    int y0 = max(0, iyc-nry), y1 = min(CSY-1, iyc+nry);
    int x0 = max(0, ixc-nrx), x1 = min(CSX-1, ixc+nrx);
    for (int iy = y0; iy <= y1; iy++) {
        int rowb = iy*CSX;
        int qs = s_cstart[rowb + x0];
        int qe = s_cstart[rowb + x1 + 1];
        for (int q = qs; q < qe; q++) {
            int i = s_clist[q];
            if (i >= r) continue;
            uint2 u = s_pc[i];
            __half2 hcc = *reinterpret_cast<__half2*>(&u.x);
            __half2 hhh = *reinterpret_cast<__half2*>(&u.y);
            float2 cc = __half22float2(hcc);
            float2 hh = __half22float2(hhh);
            if (fabsf(cc.x - mycx) < hh.x + myhx + 1.3f &&
                fabsf(cc.y - mycy) < hh.y + myhy + 1.3f) {
                float4 ob = __ldg(&g_sxy[c*KPRE + i]);
                float xx1 = fmaxf(ob.x, b.x), yy1 = fmaxf(ob.y, b.y);
                float xx2 = fminf(ob.z, b.z), yy2 = fminf(ob.w, b.w);
                float w  = __fadd_rn(__fsub_rn(xx2, xx1), 1.f);
                float h2 = __fadd_rn(__fsub_rn(yy2, yy1), 1.f);
                if (w > 0.f && h2 > 0.f) {
                    float inter = __fmul_rn(w, h2);
                    float ai = area_rn(ob.x, ob.y, ob.z, ob.w);
                    float den = __fsub_rn(__fadd_rn(ai, aj), inter);
                    if (__fdiv_rn(inter, den) > NMS_THR) {
                        if (deg < DEGG) g_edgebuf[ebase + deg] = (unsigned short)i;
                        deg++;
                    }
                }
            }
        }
    }
    g_deg[c*KPRE + r] = (unsigned char)min(deg, 255);
    if (deg > DEGG) g_overflow[c] = 1;
}

// ---------------- kernel 7c: resolve edges + extract kept ----------------
__global__ void __launch_bounds__(1024) nms_resolve() {
    extern __shared__ char dsm[];
    unsigned short*     s_edges = (unsigned short*)(dsm + ROFF_EDGES);
    unsigned short*     s_offs  = (unsigned short*)(dsm + ROFF_OFFS);
    unsigned short*     s_elist = (unsigned short*)(dsm + ROFF_ELIST);
    unsigned long long* s_keep  = (unsigned long long*)(dsm + ROFF_KEEP);
    int*                s_kept  = (int*)(dsm + ROFF_KEPT);
    int*                s_misc  = (int*)(dsm + ROFF_MISC);
    float*              s_miscf = (float*)(dsm + ROFF_MISC);

    int c = blockIdx.x, tid = threadIdx.x;
    int lane = tid & 31, wid = tid >> 5;
    const unsigned FULL = 0xFFFFFFFFu;

    int ldeg[4];
#pragma unroll
    for (int k = 0; k < 4; k++) ldeg[k] = g_deg[c*KPRE + 4*tid + k];

    int tsum = 0, ecnt = 0;
#pragma unroll
    for (int k = 0; k < 4; k++) { tsum += ldeg[k]; if (ldeg[k]) ecnt++; }
    int val = tsum | (ecnt << 20);
    int xe = val;
#pragma unroll
    for (int o = 1; o < 32; o <<= 1) { int y = __shfl_up_sync(FULL, xe, o); if (lane >= o) xe += y; }
    if (lane == 31) s_misc[wid] = xe;
    __syncthreads();
    if (wid == 0) {
        int w = s_misc[lane];
#pragma unroll
        for (int o = 1; o < 32; o <<= 1) { int y = __shfl_up_sync(FULL, w, o); if (lane >= o) w += y; }
        s_misc[lane] = w;
    }
    __syncthreads();
    bool flag = (g_overflow[c] != 0) || ((s_misc[31] & 0xFFFFF) > EDGE_CAP);
    if (!flag) {
        int xex = (wid ? s_misc[wid-1] : 0) + (xe - val);
        int eoff = xex & 0xFFFFF;
        int loff = xex >> 20;
#pragma unroll
        for (int k = 0; k < 4; k++) {
            int r = 4*tid + k;
            s_offs[r] = (unsigned short)eoff;
            size_t ebase = ((size_t)c*KPRE + r) * DEGG;
            for (int e = 0; e < ldeg[k]; e++) s_edges[eoff + e] = g_edgebuf[ebase + e];
            eoff += ldeg[k];
            if (ldeg[k]) s_elist[loff++] = (unsigned short)r;
        }
        if (tid == 1023) s_offs[KPRE] = (unsigned short)eoff;
    }
    // valid bits by rank
    if (tid < 64) {
        unsigned long long wv = 0ull;
        for (int b = 0; b < 64; b++)
            if (g_sorted_score[c*KPRE + tid*64 + b] > SCORE_THR) wv |= 1ull << b;
        s_keep[tid] = wv;
    }
    __syncthreads();

    if (!flag) {
        if (tid == 0) {
            int ne = s_misc[31] >> 20;
            for (int e2 = 0; e2 < ne; e2++) {
                int j = s_elist[e2];
                unsigned long long bitj = 1ull << (j & 63);
                if (!(s_keep[j >> 6] & bitj)) continue;
                int o = s_offs[j];
                int d = (int)s_offs[j+1] - o;
                bool dead = false;
                for (int e = 0; e < d; e++) {
                    int i = s_edges[o + e];
                    if ((s_keep[i >> 6] >> (i & 63)) & 1ull) { dead = true; break; }
                }
                if (dead) s_keep[j >> 6] &= ~bitj;
            }
        }
        __syncthreads();
        if (tid < 64) s_misc[tid] = __popcll(s_keep[tid]);
        __syncthreads();
        if (tid == 0) {
            int acc = 0;
            for (int w2 = 0; w2 < 64; w2++) { int v2 = s_misc[w2]; s_misc[w2] = acc; acc += v2; }
            s_misc[80] = acc;
        }
        __syncthreads();
        int kc = min(s_misc[80], MAXN);
        if (tid < 64) {
            unsigned long long w2 = s_keep[tid];
            int p2 = s_misc[tid];
            while (w2) {
                int b = __ffsll((long long)w2) - 1; w2 &= w2 - 1;
                if (p2 < MAXN) s_kept[p2] = tid*64 + b;
                p2++;
            }
        }
        __syncthreads();
        for (int r2 = tid; r2 < kc; r2 += 1024) {
            int rk = s_kept[r2];
            g_kept_slot[c*MAXN + r2]  = g_sorted_slot[c*KPRE + rk];
            g_kept_score[c*MAXN + r2] = g_sorted_score[c*KPRE + rk];
        }
        if (tid == 0) g_kept_cnt[c] = kc;
        return;
    }

    // --- FALLBACK: iterative greedy loop (rare; guaranteed-correct) ---
    float4 bx[4];
#pragma unroll
    for (int k = 0; k < 4; k++) bx[k] = g_sxy[c*KPRE + 4*tid + k];
    if (tid < 64) s_keep[tid] = ~s_keep[tid];      // now = removed bits
    __syncthreads();
    float* s_ref = &s_miscf[76];
    int cnt = 0, wd0 = 0;
    while (true) {
        if (tid == 0) {
            int found = -1;
            for (int wd = wd0; wd < 64; wd++) {
                unsigned long long avail = ~s_keep[wd];
                if (avail) { found = wd*64 + __ffsll((long long)avail) - 1; wd0 = wd; break; }
            }
            s_misc[75] = found;
            if (found >= 0) {
                s_keep[found >> 6] |= 1ull << (found & 63);
                s_kept[cnt] = found;
            }
        }
        __syncthreads();
        int i = s_misc[75];
        if (i < 0) break;
        if (tid == (i >> 2)) {
            int k = i & 3;
            s_ref[0] = bx[k].x; s_ref[1] = bx[k].y; s_ref[2] = bx[k].z; s_ref[3] = bx[k].w;
        }
        __syncthreads();
        float rx1 = s_ref[0], ry1 = s_ref[1], rx2 = s_ref[2], ry2 = s_ref[3];
        float ra = area_rn(rx1, ry1, rx2, ry2);
#pragma unroll
        for (int k = 0; k < 4; k++) {
            int j = 4*tid + k;
            if (j > i && !((s_keep[j >> 6] >> (j & 63)) & 1ull)) {
                float xx1 = fmaxf(rx1, bx[k].x), yy1 = fmaxf(ry1, bx[k].y);
                float xx2 = fminf(rx2, bx[k].z), yy2 = fminf(ry2, bx[k].w);
                float w  = __fadd_rn(__fsub_rn(xx2, xx1), 1.f);
                float h2 = __fadd_rn(__fsub_rn(yy2, yy1), 1.f);
                if (w > 0.f && h2 > 0.f) {
                    float inter = __fmul_rn(w, h2);
                    float ark = area_rn(bx[k].x, bx[k].y, bx[k].z, bx[k].w);
                    float den = __fsub_rn(__fadd_rn(ra, ark), inter);
                    if (__fdiv_rn(inter, den) > NMS_THR)
                        atomicOr(&s_keep[j >> 6], 1ull << (j & 63));
                }
            }
        }
        __syncthreads();
        cnt++;
        if (cnt >= MAXN) break;
    }
    for (int r2 = tid; r2 < cnt; r2 += 1024) {
        int rk = s_kept[r2];
        g_kept_slot[c*MAXN + r2]  = g_sorted_slot[c*KPRE + rk];
        g_kept_score[c*MAXN + r2] = g_sorted_score[c*KPRE + rk];
    }
    if (tid == 0) g_kept_cnt[c] = cnt;
}

// ---------------- kernel 8: merge + final top-500 + output ----------------
__global__ void __launch_bounds__(1024) final_merge(float* __restrict__ out) {
    __shared__ unsigned long long sm[2048];
    for (int t = threadIdx.x; t < 2048; t += 1024) {
        unsigned long long key = 0ull;
        if (t < 3*MAXN) {
            int c = t / MAXN, pos = t % MAXN;
            if (pos < g_kept_cnt[c]) {
                float sc = g_kept_score[c*MAXN + pos];
                unsigned flat = (unsigned)(c*KPRE + pos);
                key = ((unsigned long long)__float_as_uint(sc) << 32) | (unsigned)(~flat);
            }
        }
        sm[t] = key;
    }
    __syncthreads();
    for (unsigned k = 2; k <= 2048; k <<= 1) {
        for (unsigned j = k >> 1; j > 0; j >>= 1) {
            for (unsigned t = threadIdx.x; t < 2048; t += 1024) {
                unsigned ixj = t ^ j;
                if (ixj > t) {
                    unsigned long long A = sm[t], B = sm[ixj];
                    if ((A < B) == ((t & k) == 0)) { sm[t] = B; sm[ixj] = A; }
                }
            }
            __syncthreads();
        }
    }
    for (int r = threadIdx.x; r < MAXN; r += 1024) {
        unsigned long long key = sm[r];
        if (key != 0ull) {
            float score = __uint_as_float((unsigned)(key >> 32));
            unsigned flat = ~(unsigned)(key & 0xFFFFFFFFu);
            int c = (int)(flat >> 12);
            int pos = (int)(flat & 4095u);
            int slot = g_kept_slot[c*MAXN + pos];
            float b[7];
#pragma unroll
            for (int k = 0; k < 7; k++) b[k] = g_box[slot*7 + k];
            float rr = b[6];
            float dir_rot = __fsub_rn(__fadd_rn(rr, PIH_F),
                                      __fmul_rn(floorf(__fadd_rn(rr, 0.5f)), PI_F));
            b[6] = __fadd_rn(__fsub_rn(dir_rot, PIH_F), __fmul_rn(PI_F, g_dirf[slot]));
#pragma unroll
            for (int k = 0; k < 7; k++) out[r*7 + k] = b[k];
            out[7*MAXN + r] = score;
            out[8*MAXN + r] = (float)c;
        } else {
#pragma unroll
            for (int k = 0; k < 7; k++) out[r*7 + k] = 0.f;
            out[7*MAXN + r] = 0.f;
            out[8*MAXN + r] = -1.f;
        }
    }
}

// ---------------- launch ----------------
extern "C" void kernel_launch(void* const* d_in, const int* in_sizes, int n_in,
                              void* d_out, int out_size) {
    const float* cls    = (const float*)d_in[0];
    const float* bp     = (const float*)d_in[1];
    const float* dirp   = (const float*)d_in[2];
    const float* priors = (const float*)d_in[3];
    float* out = (float*)d_out;

    cudaFuncSetAttribute(nms_resolve, cudaFuncAttributeMaxDynamicSharedMemorySize, RDSM_TOTAL);

    zero_kernel<<<256, 256>>>();
    score_hist<<<(HW/4 + 255) / 256, 256>>>(cls);
    find_thr1<<<1, 1024>>>();
    compact1<<<(NANCH/4 + 255) / 256, 256>>>();
    level2<<<1, 1024>>>();
    sort_topk<<<1, 1024>>>();
    decode_kernel<<<(KPRE + 255) / 256, 256>>>(cls, bp, dirp, priors);
    sort_class<<<3, 1024>>>();
    nms_cells<<<3, 1024>>>();
    nms_edges<<<24, 512>>>();
    nms_resolve<<<3, 1024, RDSM_TOTAL>>>();
    final_merge<<<1, 1024>>>(out);
}